// round 3
// baseline (speedup 1.0000x reference)
#include <cuda_runtime.h>
#include <cuda_bf16.h>
#include <cstdint>

// Problem constants
#define BATCH   2
#define SEQ     2048
#define NHEADS  16
#define DHEAD   64
#define DMODEL  1024           // NHEADS*DHEAD
#define ATTN_SCALE_INV 0.125f  // 1/sqrt(64)

// Scratch for z = attention output, layout [B, S, H*D] = [4096, 1024]
__device__ float g_zbuf[BATCH * SEQ * DMODEL];

// ---------------------------------------------------------------------------
// Residual passthrough: out[0 : B*S*DMODEL] = residual
// ---------------------------------------------------------------------------
__global__ __launch_bounds__(256)
void copy_kernel(const float* __restrict__ src, float* __restrict__ dst, int n4)
{
    int i = blockIdx.x * blockDim.x + threadIdx.x;
    if (i < n4) ((float4*)dst)[i] = ((const float4*)src)[i];
}

// ---------------------------------------------------------------------------
// Flash-attention (fp32). One thread owns one q row. 128 q rows per block.
// K/V streamed through shared in 64-row tiles. Streaming softmax with
// branch-guarded rescale (max updates are ~log(S) per row => cheap).
// ---------------------------------------------------------------------------
__global__
void attn_kernel(const float* __restrict__ q,
                 const float* __restrict__ k,
                 const float* __restrict__ v)
{
    const int b  = blockIdx.z;
    const int h  = blockIdx.y;
    const int q0 = blockIdx.x * 128;
    const int tid = threadIdx.x;           // 0..127
    const int qr  = q0 + tid;              // this thread's q row

    __shared__ float Ks[64][64];
    __shared__ float Vs[64][64];

    // Load q row into registers, pre-scaled
    float qreg[DHEAD];
    {
        const float* qptr = q + ((size_t)b * SEQ + qr) * DMODEL + h * DHEAD;
        const float4* q4 = (const float4*)qptr;
        #pragma unroll
        for (int d4 = 0; d4 < 16; d4++) {
            float4 t = q4[d4];
            qreg[4*d4+0] = t.x * ATTN_SCALE_INV;
            qreg[4*d4+1] = t.y * ATTN_SCALE_INV;
            qreg[4*d4+2] = t.z * ATTN_SCALE_INV;
            qreg[4*d4+3] = t.w * ATTN_SCALE_INV;
        }
    }

    float acc[DHEAD];
    #pragma unroll
    for (int d = 0; d < DHEAD; d++) acc[d] = 0.f;
    float m = -1e30f, l = 0.f;

    const float* kbase = k + ((size_t)b * SEQ) * DMODEL + h * DHEAD;
    const float* vbase = v + ((size_t)b * SEQ) * DMODEL + h * DHEAD;

    const int ktiles = (q0 + 128) / 64;    // tiles needed to cover causal range

    for (int kt = 0; kt < ktiles; kt++) {
        const int kb = kt * 64;
        __syncthreads();
        // Cooperative tile load: 64x64 floats each for K and V, float4 vectorized
        for (int i = tid; i < 64 * 16; i += 128) {
            int r = i >> 4;
            int c = (i & 15) * 4;
            *(float4*)&Ks[r][c] = *(const float4*)&kbase[(size_t)(kb + r) * DMODEL + c];
            *(float4*)&Vs[r][c] = *(const float4*)&vbase[(size_t)(kb + r) * DMODEL + c];
        }
        __syncthreads();

        if (kb > qr) continue;             // entirely above diagonal for this row
        const int kmax = (kb + 63 > qr) ? (qr - kb) : 63;

        for (int kk = 0; kk <= kmax; kk++) {
            // dot(q, K[kk])
            float s = 0.f;
            const float4* krow = (const float4*)Ks[kk];
            #pragma unroll
            for (int d4 = 0; d4 < 16; d4++) {
                float4 kv = krow[d4];
                s += qreg[4*d4+0] * kv.x;
                s += qreg[4*d4+1] * kv.y;
                s += qreg[4*d4+2] * kv.z;
                s += qreg[4*d4+3] * kv.w;
            }
            if (s > m) {
                float corr = __expf(m - s);
                m = s;
                l *= corr;
                #pragma unroll
                for (int d = 0; d < DHEAD; d++) acc[d] *= corr;
            }
            float e = __expf(s - m);
            l += e;
            const float4* vrow = (const float4*)Vs[kk];
            #pragma unroll
            for (int d4 = 0; d4 < 16; d4++) {
                float4 vv = vrow[d4];
                acc[4*d4+0] += e * vv.x;
                acc[4*d4+1] += e * vv.y;
                acc[4*d4+2] += e * vv.z;
                acc[4*d4+3] += e * vv.w;
            }
        }
    }

    const float inv = 1.f / l;
    float* zp = g_zbuf + ((size_t)b * SEQ + qr) * DMODEL + h * DHEAD;
    #pragma unroll
    for (int d4 = 0; d4 < 16; d4++) {
        float4 o;
        o.x = acc[4*d4+0] * inv;
        o.y = acc[4*d4+1] * inv;
        o.z = acc[4*d4+2] * inv;
        o.w = acc[4*d4+3] * inv;
        *(float4*)&zp[4*d4] = o;
    }
}

// ---------------------------------------------------------------------------
// SGEMM: C[M,N] = g_zbuf[M,K] @ B[K,N] + bias[N]
// 128x128 block tile, BK=8, 256 threads, 8x8 microtile per thread.
// M = 4096, N = K = 1024 (all compile-time).
// ---------------------------------------------------------------------------
#define GM 128
#define GN 128
#define GK 8
#define GEMM_M (BATCH * SEQ)
#define GEMM_N DMODEL
#define GEMM_K DMODEL

__global__ __launch_bounds__(256)
void gemm_kernel(const float* __restrict__ B,
                 const float* __restrict__ bias,
                 float* __restrict__ C)
{
    __shared__ float As[GK][GM];
    __shared__ float Bs[GK][GN];

    const int tid = threadIdx.x;           // 0..255
    const int bm = blockIdx.y * GM;
    const int bn = blockIdx.x * GN;
    const int tx = tid & 15;               // 0..15 -> N microtile
    const int ty = tid >> 4;               // 0..15 -> M microtile

    // Loader mapping
    const int arow = tid >> 1;             // 0..127
    const int acol = (tid & 1) * 4;        // 0 or 4
    const int brow = tid >> 5;             // 0..7
    const int bcol = (tid & 31) * 4;       // 0..124

    const float* Aptr = g_zbuf + (size_t)(bm + arow) * GEMM_K + acol;
    const float* Bptr = B + (size_t)brow * GEMM_N + bn + bcol;

    float acc[8][8];
    #pragma unroll
    for (int i = 0; i < 8; i++)
        #pragma unroll
        for (int j = 0; j < 8; j++) acc[i][j] = 0.f;

    for (int k0 = 0; k0 < GEMM_K; k0 += GK) {
        float4 a4 = *(const float4*)(Aptr + k0);
        float4 b4 = *(const float4*)(Bptr + (size_t)k0 * GEMM_N);
        __syncthreads();
        As[acol + 0][arow] = a4.x;
        As[acol + 1][arow] = a4.y;
        As[acol + 2][arow] = a4.z;
        As[acol + 3][arow] = a4.w;
        *(float4*)&Bs[brow][bcol] = b4;
        __syncthreads();

        #pragma unroll
        for (int kk = 0; kk < GK; kk++) {
            float a[8], bb[8];
            #pragma unroll
            for (int i = 0; i < 8; i += 4)
                *(float4*)&a[i] = *(const float4*)&As[kk][ty * 8 + i];
            #pragma unroll
            for (int j = 0; j < 8; j += 4)
                *(float4*)&bb[j] = *(const float4*)&Bs[kk][tx * 8 + j];
            #pragma unroll
            for (int i = 0; i < 8; i++)
                #pragma unroll
                for (int j = 0; j < 8; j++)
                    acc[i][j] += a[i] * bb[j];
        }
    }

    // Epilogue: add bias, store
    #pragma unroll
    for (int i = 0; i < 8; i++) {
        float* crow = C + (size_t)(bm + ty * 8 + i) * GEMM_N + bn + tx * 8;
        #pragma unroll
        for (int j = 0; j < 8; j += 4) {
            float4 o;
            o.x = acc[i][j + 0] + bias[bn + tx * 8 + j + 0];
            o.y = acc[i][j + 1] + bias[bn + tx * 8 + j + 1];
            o.z = acc[i][j + 2] + bias[bn + tx * 8 + j + 2];
            o.w = acc[i][j + 3] + bias[bn + tx * 8 + j + 3];
            *(float4*)&crow[j] = o;
        }
    }
}

// ---------------------------------------------------------------------------
// Launch
// ---------------------------------------------------------------------------
extern "C" void kernel_launch(void* const* d_in, const int* in_sizes, int n_in,
                              void* d_out, int out_size)
{
    const float* residual = (const float*)d_in[0];
    const float* q        = (const float*)d_in[1];
    const float* k        = (const float*)d_in[2];
    const float* v        = (const float*)d_in[3];
    const float* W_O      = (const float*)d_in[4];  // [H,D,M] == [1024,1024] row-major
    const float* b_O      = (const float*)d_in[5];

    float* out = (float*)d_out;
    const int res_elems = BATCH * SEQ * DMODEL;     // 4,194,304

    // Output 0: residual passthrough (float4 copy kernel)
    const int n4 = res_elems / 4;
    copy_kernel<<<(n4 + 255) / 256, 256>>>(residual, out, n4);

    // Attention -> g_zbuf
    dim3 agrid(SEQ / 128, NHEADS, BATCH);
    attn_kernel<<<agrid, 128>>>(q, k, v);

    // Projection: out = g_zbuf @ W_O + b_O   (M=4096, N=1024, K=1024)
    dim3 ggrid(GEMM_N / GN, GEMM_M / GM);
    gemm_kernel<<<ggrid, 256>>>(W_O, b_O, out + res_elems);
}

// round 5
// speedup vs baseline: 1.0929x; 1.0929x over previous
#include <cuda_runtime.h>
#include <cuda_bf16.h>
#include <cstdint>

// Problem constants
#define BATCH   2
#define SEQ     2048
#define NHEADS  16
#define DHEAD   64
#define DMODEL  1024
#define ATTN_SCALE_INV 0.125f

// bf16 hi/lo split operand buffers
__device__ __nv_bfloat16 g_ahi[BATCH * SEQ * DMODEL];   // z hi  [M=4096, K=1024]
__device__ __nv_bfloat16 g_alo[BATCH * SEQ * DMODEL];   // z lo
__device__ __nv_bfloat16 g_bhi[DMODEL * DMODEL];        // W_O^T hi [N=1024, K=1024]
__device__ __nv_bfloat16 g_blo[DMODEL * DMODEL];        // W_O^T lo

// ---------------------------------------------------------------------------
// mma.sync m16n8k16 bf16 (portable PTX, works on .target sm_100)
// ---------------------------------------------------------------------------
__device__ __forceinline__ void mma16816(float* c, const uint32_t* a, const uint32_t* b)
{
    asm volatile(
        "mma.sync.aligned.m16n8k16.row.col.f32.bf16.bf16.f32 "
        "{%0,%1,%2,%3}, {%4,%5,%6,%7}, {%8,%9}, {%0,%1,%2,%3};"
        : "+f"(c[0]), "+f"(c[1]), "+f"(c[2]), "+f"(c[3])
        : "r"(a[0]), "r"(a[1]), "r"(a[2]), "r"(a[3]), "r"(b[0]), "r"(b[1]));
}

// ---------------------------------------------------------------------------
// Residual passthrough
// ---------------------------------------------------------------------------
__global__ __launch_bounds__(256)
void copy_kernel(const float* __restrict__ src, float* __restrict__ dst, int n4)
{
    int i = blockIdx.x * blockDim.x + threadIdx.x;
    if (i < n4) ((float4*)dst)[i] = ((const float4*)src)[i];
}

// ---------------------------------------------------------------------------
// W_O transpose + hi/lo bf16 split: in [K=1024, N=1024] -> out [N, K]
// ---------------------------------------------------------------------------
__global__ __launch_bounds__(256)
void wsplit_kernel(const float* __restrict__ W)
{
    __shared__ float tile[32][33];
    const int bx = blockIdx.x * 32;   // n
    const int by = blockIdx.y * 32;   // k
    const int tx = threadIdx.x;       // 0..31
    const int ty = threadIdx.y;       // 0..7
    #pragma unroll
    for (int r = 0; r < 32; r += 8)
        tile[ty + r][tx] = W[(size_t)(by + ty + r) * DMODEL + bx + tx];
    __syncthreads();
    #pragma unroll
    for (int r = 0; r < 32; r += 8) {
        float f = tile[tx][ty + r];
        int n = bx + ty + r, kk = by + tx;
        __nv_bfloat16 h = __float2bfloat16(f);
        __nv_bfloat16 l = __float2bfloat16(f - __bfloat162float(h));
        g_bhi[(size_t)n * DMODEL + kk] = h;
        g_blo[(size_t)n * DMODEL + kk] = l;
    }
}

// ---------------------------------------------------------------------------
// Flash-attention (fp32 SIMT). Epilogue writes bf16 hi/lo split directly.
// ---------------------------------------------------------------------------
__global__
void attn_kernel(const float* __restrict__ q,
                 const float* __restrict__ k,
                 const float* __restrict__ v)
{
    const int b  = blockIdx.z;
    const int h  = blockIdx.y;
    const int q0 = blockIdx.x * 128;
    const int tid = threadIdx.x;
    const int qr  = q0 + tid;

    __shared__ float Ks[64][64];
    __shared__ float Vs[64][64];

    float qreg[DHEAD];
    {
        const float4* q4 = (const float4*)(q + ((size_t)b * SEQ + qr) * DMODEL + h * DHEAD);
        #pragma unroll
        for (int d4 = 0; d4 < 16; d4++) {
            float4 t = q4[d4];
            qreg[4*d4+0] = t.x * ATTN_SCALE_INV;
            qreg[4*d4+1] = t.y * ATTN_SCALE_INV;
            qreg[4*d4+2] = t.z * ATTN_SCALE_INV;
            qreg[4*d4+3] = t.w * ATTN_SCALE_INV;
        }
    }

    float acc[DHEAD];
    #pragma unroll
    for (int d = 0; d < DHEAD; d++) acc[d] = 0.f;
    float m = -1e30f, l = 0.f;

    const float* kbase = k + ((size_t)b * SEQ) * DMODEL + h * DHEAD;
    const float* vbase = v + ((size_t)b * SEQ) * DMODEL + h * DHEAD;

    const int ktiles = (q0 + 128) / 64;

    for (int kt = 0; kt < ktiles; kt++) {
        const int kb = kt * 64;
        __syncthreads();
        for (int i = tid; i < 64 * 16; i += 128) {
            int r = i >> 4;
            int c = (i & 15) * 4;
            *(float4*)&Ks[r][c] = *(const float4*)&kbase[(size_t)(kb + r) * DMODEL + c];
            *(float4*)&Vs[r][c] = *(const float4*)&vbase[(size_t)(kb + r) * DMODEL + c];
        }
        __syncthreads();

        if (kb > qr) continue;
        const int kmax = (kb + 63 > qr) ? (qr - kb) : 63;

        for (int kk = 0; kk <= kmax; kk++) {
            float s = 0.f;
            const float4* krow = (const float4*)Ks[kk];
            #pragma unroll
            for (int d4 = 0; d4 < 16; d4++) {
                float4 kv = krow[d4];
                s += qreg[4*d4+0] * kv.x;
                s += qreg[4*d4+1] * kv.y;
                s += qreg[4*d4+2] * kv.z;
                s += qreg[4*d4+3] * kv.w;
            }
            if (s > m) {
                float corr = __expf(m - s);
                m = s;
                l *= corr;
                #pragma unroll
                for (int d = 0; d < DHEAD; d++) acc[d] *= corr;
            }
            float e = __expf(s - m);
            l += e;
            const float4* vrow = (const float4*)Vs[kk];
            #pragma unroll
            for (int d4 = 0; d4 < 16; d4++) {
                float4 vv = vrow[d4];
                acc[4*d4+0] += e * vv.x;
                acc[4*d4+1] += e * vv.y;
                acc[4*d4+2] += e * vv.z;
                acc[4*d4+3] += e * vv.w;
            }
        }
    }

    const float inv = 1.f / l;
    const size_t zoff = ((size_t)b * SEQ + qr) * DMODEL + h * DHEAD;
    #pragma unroll
    for (int d4 = 0; d4 < 16; d4++) {
        alignas(8) __nv_bfloat16 hh[4];
        alignas(8) __nv_bfloat16 ll[4];
        #pragma unroll
        for (int j = 0; j < 4; j++) {
            float o = acc[4*d4+j] * inv;
            __nv_bfloat16 hb = __float2bfloat16(o);
            hh[j] = hb;
            ll[j] = __float2bfloat16(o - __bfloat162float(hb));
        }
        *(uint2*)&g_ahi[zoff + 4*d4] = *(uint2*)hh;
        *(uint2*)&g_alo[zoff + 4*d4] = *(uint2*)ll;
    }
}

// ---------------------------------------------------------------------------
// Tensor-core projection GEMM (mma.sync bf16, 3-term precision split):
//   C[M=4096, N=1024] = (Ah+Al)[M,K] @ (Bh+Bl)^T[N,K] + bias[N]
// CTA tile 128x128, K-chunk 32, 8 warps (warp tile 32x64), reg double buffer.
// SMEM rows padded to 40 bf16 (80B) -> conflict-free fragment LDS.
// ---------------------------------------------------------------------------
#define TK       32
#define NCHUNK   (DMODEL / TK)        // 32
#define ROWP     40                   // padded row, bf16 elems
#define MAT_BYTES (128 * ROWP * 2)    // 10240
#define STAGE_BYTES (4 * MAT_BYTES)   // 40960

__global__ __launch_bounds__(256, 1)
void gemm_tc_kernel(const float* __restrict__ bias, float* __restrict__ C)
{
    extern __shared__ __align__(16) char smem[];

    const int tid  = threadIdx.x;
    const int wid  = tid >> 5;
    const int lane = tid & 31;
    const int bm = blockIdx.y * 128;
    const int bn = blockIdx.x * 128;

    const int wm = (wid & 3) * 32;    // warp m offset in tile
    const int wn = (wid >> 2) * 64;   // warp n offset in tile

    const int g  = lane >> 2;         // 0..7
    const int t2 = (lane & 3) * 2;    // 0,2,4,6

    float acc[2][8][4];
    #pragma unroll
    for (int mt = 0; mt < 2; mt++)
        #pragma unroll
        for (int nt = 0; nt < 8; nt++)
            #pragma unroll
            for (int r = 0; r < 4; r++) acc[mt][nt][r] = 0.f;

    // Staging geometry: per matrix 2 uint4 per thread
    const int u0 = tid * 2;
    const int srow0 = u0 >> 2, scol0 = (u0 & 3) * 8;      // bf16 col
    const int srow1 = (u0 + 1) >> 2, scol1 = ((u0 + 1) & 3) * 8;

    const __nv_bfloat16* gA[2] = { g_ahi, g_alo };
    const __nv_bfloat16* gB[2] = { g_bhi, g_blo };

    uint4 st[8];

    // Prologue: load chunk 0
    #pragma unroll
    for (int mx = 0; mx < 2; mx++) {
        st[mx*2+0] = *(const uint4*)(gA[mx] + (size_t)(bm + srow0) * DMODEL + scol0);
        st[mx*2+1] = *(const uint4*)(gA[mx] + (size_t)(bm + srow1) * DMODEL + scol1);
        st[4+mx*2+0] = *(const uint4*)(gB[mx] + (size_t)(bn + srow0) * DMODEL + scol0);
        st[4+mx*2+1] = *(const uint4*)(gB[mx] + (size_t)(bn + srow1) * DMODEL + scol1);
    }
    {
        char* base = smem;
        #pragma unroll
        for (int mtx = 0; mtx < 4; mtx++) {
            *(uint4*)(base + mtx*MAT_BYTES + srow0*(ROWP*2) + scol0*2) = st[mtx*2+0];
            *(uint4*)(base + mtx*MAT_BYTES + srow1*(ROWP*2) + scol1*2) = st[mtx*2+1];
        }
    }
    __syncthreads();

    for (int kc = 0; kc < NCHUNK; kc++) {
        const int cur = kc & 1;
        const bool more = (kc + 1 < NCHUNK);

        // Issue loads for next chunk early
        if (more) {
            const int kb = (kc + 1) * TK;
            #pragma unroll
            for (int mx = 0; mx < 2; mx++) {
                st[mx*2+0] = *(const uint4*)(gA[mx] + (size_t)(bm + srow0) * DMODEL + kb + scol0);
                st[mx*2+1] = *(const uint4*)(gA[mx] + (size_t)(bm + srow1) * DMODEL + kb + scol1);
                st[4+mx*2+0] = *(const uint4*)(gB[mx] + (size_t)(bn + srow0) * DMODEL + kb + scol0);
                st[4+mx*2+1] = *(const uint4*)(gB[mx] + (size_t)(bn + srow1) * DMODEL + kb + scol1);
            }
        }

        // Compute on current stage
        const __nv_bfloat16* Ah = (const __nv_bfloat16*)(smem + cur*STAGE_BYTES);
        const __nv_bfloat16* Al = (const __nv_bfloat16*)(smem + cur*STAGE_BYTES + MAT_BYTES);
        const __nv_bfloat16* Bh = (const __nv_bfloat16*)(smem + cur*STAGE_BYTES + 2*MAT_BYTES);
        const __nv_bfloat16* Bl = (const __nv_bfloat16*)(smem + cur*STAGE_BYTES + 3*MAT_BYTES);

        #pragma unroll
        for (int ks = 0; ks < 2; ks++) {
            const int k0 = ks * 16;
            uint32_t ah[2][4], al[2][4], bh[8][2], bl[8][2];
            #pragma unroll
            for (int mt = 0; mt < 2; mt++) {
                const int r0 = wm + mt * 16 + g;
                ah[mt][0] = *(const uint32_t*)&Ah[r0 * ROWP + k0 + t2];
                ah[mt][1] = *(const uint32_t*)&Ah[(r0 + 8) * ROWP + k0 + t2];
                ah[mt][2] = *(const uint32_t*)&Ah[r0 * ROWP + k0 + t2 + 8];
                ah[mt][3] = *(const uint32_t*)&Ah[(r0 + 8) * ROWP + k0 + t2 + 8];
                al[mt][0] = *(const uint32_t*)&Al[r0 * ROWP + k0 + t2];
                al[mt][1] = *(const uint32_t*)&Al[(r0 + 8) * ROWP + k0 + t2];
                al[mt][2] = *(const uint32_t*)&Al[r0 * ROWP + k0 + t2 + 8];
                al[mt][3] = *(const uint32_t*)&Al[(r0 + 8) * ROWP + k0 + t2 + 8];
            }
            #pragma unroll
            for (int nt = 0; nt < 8; nt++) {
                const int n0 = wn + nt * 8 + g;
                bh[nt][0] = *(const uint32_t*)&Bh[n0 * ROWP + k0 + t2];
                bh[nt][1] = *(const uint32_t*)&Bh[n0 * ROWP + k0 + t2 + 8];
                bl[nt][0] = *(const uint32_t*)&Bl[n0 * ROWP + k0 + t2];
                bl[nt][1] = *(const uint32_t*)&Bl[n0 * ROWP + k0 + t2 + 8];
            }
            #pragma unroll
            for (int mt = 0; mt < 2; mt++)
                #pragma unroll
                for (int nt = 0; nt < 8; nt++) {
                    mma16816(acc[mt][nt], ah[mt], bh[nt]);
                    mma16816(acc[mt][nt], ah[mt], bl[nt]);
                    mma16816(acc[mt][nt], al[mt], bh[nt]);
                }
        }

        // Store next chunk into other stage
        if (more) {
            char* base = smem + (cur ^ 1) * STAGE_BYTES;
            #pragma unroll
            for (int mtx = 0; mtx < 4; mtx++) {
                *(uint4*)(base + mtx*MAT_BYTES + srow0*(ROWP*2) + scol0*2) = st[mtx*2+0];
                *(uint4*)(base + mtx*MAT_BYTES + srow1*(ROWP*2) + scol1*2) = st[mtx*2+1];
            }
            __syncthreads();
        }
    }

    // Epilogue
    #pragma unroll
    for (int mt = 0; mt < 2; mt++) {
        const int row0 = bm + wm + mt * 16 + g;
        #pragma unroll
        for (int nt = 0; nt < 8; nt++) {
            const int col0 = bn + wn + nt * 8 + t2;
            const float b0 = bias[col0], b1 = bias[col0 + 1];
            float2 o01 = { acc[mt][nt][0] + b0, acc[mt][nt][1] + b1 };
            float2 o23 = { acc[mt][nt][2] + b0, acc[mt][nt][3] + b1 };
            *(float2*)(C + (size_t)row0 * DMODEL + col0) = o01;
            *(float2*)(C + (size_t)(row0 + 8) * DMODEL + col0) = o23;
        }
    }
}

// ---------------------------------------------------------------------------
// Launch
// ---------------------------------------------------------------------------
extern "C" void kernel_launch(void* const* d_in, const int* in_sizes, int n_in,
                              void* d_out, int out_size)
{
    const float* residual = (const float*)d_in[0];
    const float* q        = (const float*)d_in[1];
    const float* k        = (const float*)d_in[2];
    const float* v        = (const float*)d_in[3];
    const float* W_O      = (const float*)d_in[4];
    const float* b_O      = (const float*)d_in[5];

    float* out = (float*)d_out;
    const int res_elems = BATCH * SEQ * DMODEL;

    const int n4 = res_elems / 4;
    copy_kernel<<<(n4 + 255) / 256, 256>>>(residual, out, n4);

    // W_O transpose + split (independent of attention)
    wsplit_kernel<<<dim3(32, 32), dim3(32, 8)>>>(W_O);

    // Attention -> g_ahi/g_alo (bf16 hi/lo split of z)
    dim3 agrid(SEQ / 128, NHEADS, BATCH);
    attn_kernel<<<agrid, 128>>>(q, k, v);

    // Tensor-core projection
    const int dyn = 2 * STAGE_BYTES;   // 80 KB
    cudaFuncSetAttribute(gemm_tc_kernel,
                         cudaFuncAttributeMaxDynamicSharedMemorySize, dyn);
    gemm_tc_kernel<<<dim3(DMODEL / 128, (BATCH * SEQ) / 128), 256, dyn>>>(
        b_O, out + res_elems);
}

// round 6
// speedup vs baseline: 2.8401x; 2.5986x over previous
#include <cuda_runtime.h>
#include <cuda_bf16.h>
#include <cstdint>

// Problem constants
#define BATCH   2
#define SEQ     2048
#define NHEADS  16
#define DHEAD   64
#define DMODEL  1024
#define ATTN_SCALE_INV 0.125f

// bf16 hi/lo split operand buffers
__device__ __nv_bfloat16 g_ahi[BATCH * SEQ * DMODEL];   // z hi  [M=4096, K=1024]
__device__ __nv_bfloat16 g_alo[BATCH * SEQ * DMODEL];   // z lo
__device__ __nv_bfloat16 g_bhi[DMODEL * DMODEL];        // W_O^T hi [N=1024, K=1024]
__device__ __nv_bfloat16 g_blo[DMODEL * DMODEL];        // W_O^T lo

// ---------------------------------------------------------------------------
// mma.sync m16n8k16 bf16 (portable PTX, works on .target sm_100)
// ---------------------------------------------------------------------------
__device__ __forceinline__ void mma16816(float* c, const uint32_t* a, const uint32_t* b)
{
    asm volatile(
        "mma.sync.aligned.m16n8k16.row.col.f32.bf16.bf16.f32 "
        "{%0,%1,%2,%3}, {%4,%5,%6,%7}, {%8,%9}, {%0,%1,%2,%3};"
        : "+f"(c[0]), "+f"(c[1]), "+f"(c[2]), "+f"(c[3])
        : "r"(a[0]), "r"(a[1]), "r"(a[2]), "r"(a[3]), "r"(b[0]), "r"(b[1]));
}

// Split (a,b) fp32 pair into packed bf16x2 hi + lo residual
__device__ __forceinline__ void split2(float a, float b, uint32_t& hi, uint32_t& lo)
{
    __nv_bfloat162 h2 = __floats2bfloat162_rn(a, b);
    float ra = a - __bfloat162float(h2.x);
    float rb = b - __bfloat162float(h2.y);
    __nv_bfloat162 l2 = __floats2bfloat162_rn(ra, rb);
    hi = *(uint32_t*)&h2;
    lo = *(uint32_t*)&l2;
}

// ---------------------------------------------------------------------------
// Residual passthrough
// ---------------------------------------------------------------------------
__global__ __launch_bounds__(256)
void copy_kernel(const float* __restrict__ src, float* __restrict__ dst, int n4)
{
    int i = blockIdx.x * blockDim.x + threadIdx.x;
    if (i < n4) ((float4*)dst)[i] = ((const float4*)src)[i];
}

// ---------------------------------------------------------------------------
// W_O transpose + hi/lo bf16 split: in [K=1024, N=1024] -> out [N, K]
// ---------------------------------------------------------------------------
__global__ __launch_bounds__(256)
void wsplit_kernel(const float* __restrict__ W)
{
    __shared__ float tile[32][33];
    const int bx = blockIdx.x * 32;   // n
    const int by = blockIdx.y * 32;   // k
    const int tx = threadIdx.x;       // 0..31
    const int ty = threadIdx.y;       // 0..7
    #pragma unroll
    for (int r = 0; r < 32; r += 8)
        tile[ty + r][tx] = W[(size_t)(by + ty + r) * DMODEL + bx + tx];
    __syncthreads();
    #pragma unroll
    for (int r = 0; r < 32; r += 8) {
        float f = tile[tx][ty + r];
        int n = bx + ty + r, kk = by + tx;
        __nv_bfloat16 h = __float2bfloat16(f);
        __nv_bfloat16 l = __float2bfloat16(f - __bfloat162float(h));
        g_bhi[(size_t)n * DMODEL + kk] = h;
        g_blo[(size_t)n * DMODEL + kk] = l;
    }
}

// ---------------------------------------------------------------------------
// Tensor-core flash attention (mma.sync bf16, 3-term split for both GEMMs).
// Grid: (qtile=16 reversed, h=16, b=2). Block 256 = 8 warps x 16 q-rows.
// K tile [128 kpos][64 d] (row stride 72), Vt tile [64 d][128 kpos] (stride 136).
// ---------------------------------------------------------------------------
#define KROWP 72
#define VROWP 136
#define ATT_SMEM ((2 * 128 * KROWP + 2 * 64 * VROWP) * 2)   // 71680 bytes

__global__ __launch_bounds__(256, 1)
void attn_tc_kernel(const float* __restrict__ q,
                    const float* __restrict__ k,
                    const float* __restrict__ v)
{
    extern __shared__ __align__(16) char smem[];
    __nv_bfloat16* Kh  = (__nv_bfloat16*)smem;          // [128][72]
    __nv_bfloat16* Kl  = Kh + 128 * KROWP;
    __nv_bfloat16* Vth = Kl + 128 * KROWP;              // [64][136]
    __nv_bfloat16* Vtl = Vth + 64 * VROWP;

    const int b   = blockIdx.z;
    const int h   = blockIdx.y;
    const int qt  = (int)(gridDim.x - 1) - (int)blockIdx.x;   // big work first
    const int tid = threadIdx.x;
    const int wid = tid >> 5;
    const int lane = tid & 31;
    const int g   = lane >> 2;
    const int t2  = (lane & 3) * 2;
    const int wm  = wid * 16;

    const float* kbase = k + (size_t)b * SEQ * DMODEL + h * DHEAD;
    const float* vbase = v + (size_t)b * SEQ * DMODEL + h * DHEAD;

    // ---- Q fragments (register resident, pre-scaled, hi/lo split) ----
    uint32_t qh[4][4], ql[4][4];
    {
        const float* qb = q + (size_t)b * SEQ * DMODEL + h * DHEAD;
        const int r0 = qt * 128 + wm + g;
        #pragma unroll
        for (int kc = 0; kc < 4; kc++) {
            #pragma unroll
            for (int a = 0; a < 4; a++) {
                int row = r0 + ((a & 1) ? 8 : 0);
                int col = kc * 16 + t2 + ((a >= 2) ? 8 : 0);
                float2 f = *(const float2*)(qb + (size_t)row * DMODEL + col);
                split2(f.x * ATTN_SCALE_INV, f.y * ATTN_SCALE_INV, qh[kc][a], ql[kc][a]);
            }
        }
    }

    float oacc[8][4];
    #pragma unroll
    for (int nt = 0; nt < 8; nt++)
        #pragma unroll
        for (int r = 0; r < 4; r++) oacc[nt][r] = 0.f;
    float m0 = -1e30f, m1 = -1e30f, l0 = 0.f, l1 = 0.f;

    for (int kt = 0; kt <= qt; kt++) {
        __syncthreads();
        // ---- load + convert K tile ----
        for (int i = tid; i < 128 * 16; i += 256) {
            int row = i >> 4, c4 = (i & 15) * 4;
            float4 f = *(const float4*)(kbase + (size_t)(kt * 128 + row) * DMODEL + c4);
            uint32_t h0, lo0, h1, lo1;
            split2(f.x, f.y, h0, lo0);
            split2(f.z, f.w, h1, lo1);
            uint32_t* kh = (uint32_t*)(Kh + row * KROWP + c4);
            uint32_t* kl = (uint32_t*)(Kl + row * KROWP + c4);
            kh[0] = h0; kh[1] = h1;
            kl[0] = lo0; kl[1] = lo1;
        }
        // ---- load + convert + transpose V tile ----
        for (int i = tid; i < 64 * 16; i += 256) {
            int kpp = i & 63, dch = i >> 6;
            const float* v0 = vbase + (size_t)(kt * 128 + 2 * kpp) * DMODEL + dch * 4;
            float4 a = *(const float4*)v0;
            float4 c = *(const float4*)(v0 + DMODEL);
            uint32_t hh, ll;
            split2(a.x, c.x, hh, ll);
            ((uint32_t*)(Vth + (dch*4+0) * VROWP))[kpp] = hh;
            ((uint32_t*)(Vtl + (dch*4+0) * VROWP))[kpp] = ll;
            split2(a.y, c.y, hh, ll);
            ((uint32_t*)(Vth + (dch*4+1) * VROWP))[kpp] = hh;
            ((uint32_t*)(Vtl + (dch*4+1) * VROWP))[kpp] = ll;
            split2(a.z, c.z, hh, ll);
            ((uint32_t*)(Vth + (dch*4+2) * VROWP))[kpp] = hh;
            ((uint32_t*)(Vtl + (dch*4+2) * VROWP))[kpp] = ll;
            split2(a.w, c.w, hh, ll);
            ((uint32_t*)(Vth + (dch*4+3) * VROWP))[kpp] = hh;
            ((uint32_t*)(Vtl + (dch*4+3) * VROWP))[kpp] = ll;
        }
        __syncthreads();

        // ---- S = Q @ K^T (3-term split) ----
        float sacc[16][4];
        #pragma unroll
        for (int nt = 0; nt < 16; nt++) {
            #pragma unroll
            for (int r = 0; r < 4; r++) sacc[nt][r] = 0.f;
            #pragma unroll
            for (int kc = 0; kc < 4; kc++) {
                const __nv_bfloat16* kr = Kh + (nt * 8 + g) * KROWP + kc * 16 + t2;
                const __nv_bfloat16* lr = Kl + (nt * 8 + g) * KROWP + kc * 16 + t2;
                uint32_t bh[2] = { *(const uint32_t*)kr, *(const uint32_t*)(kr + 8) };
                uint32_t bl[2] = { *(const uint32_t*)lr, *(const uint32_t*)(lr + 8) };
                mma16816(sacc[nt], qh[kc], bh);
                mma16816(sacc[nt], qh[kc], bl);
                mma16816(sacc[nt], ql[kc], bh);
            }
        }

        // ---- causal mask (diagonal tile only) ----
        if (kt == qt) {
            const int rl0 = wm + g, rl1 = rl0 + 8;
            #pragma unroll
            for (int nt = 0; nt < 16; nt++) {
                int c0 = nt * 8 + t2;
                if (c0     > rl0) sacc[nt][0] = -1e30f;
                if (c0 + 1 > rl0) sacc[nt][1] = -1e30f;
                if (c0     > rl1) sacc[nt][2] = -1e30f;
                if (c0 + 1 > rl1) sacc[nt][3] = -1e30f;
            }
        }

        // ---- online softmax ----
        float mx0 = -1e30f, mx1 = -1e30f;
        #pragma unroll
        for (int nt = 0; nt < 16; nt++) {
            mx0 = fmaxf(mx0, fmaxf(sacc[nt][0], sacc[nt][1]));
            mx1 = fmaxf(mx1, fmaxf(sacc[nt][2], sacc[nt][3]));
        }
        mx0 = fmaxf(mx0, __shfl_xor_sync(0xffffffffu, mx0, 1));
        mx0 = fmaxf(mx0, __shfl_xor_sync(0xffffffffu, mx0, 2));
        mx1 = fmaxf(mx1, __shfl_xor_sync(0xffffffffu, mx1, 1));
        mx1 = fmaxf(mx1, __shfl_xor_sync(0xffffffffu, mx1, 2));

        float mn0 = fmaxf(m0, mx0), mn1 = fmaxf(m1, mx1);
        float c0 = __expf(m0 - mn0), c1 = __expf(m1 - mn1);
        m0 = mn0; m1 = mn1;
        l0 *= c0; l1 *= c1;
        #pragma unroll
        for (int nt = 0; nt < 8; nt++) {
            oacc[nt][0] *= c0; oacc[nt][1] *= c0;
            oacc[nt][2] *= c1; oacc[nt][3] *= c1;
        }

        float ls0 = 0.f, ls1 = 0.f;
        #pragma unroll
        for (int nt = 0; nt < 16; nt++) {
            float p0 = __expf(sacc[nt][0] - m0);
            float p1 = __expf(sacc[nt][1] - m0);
            float p2 = __expf(sacc[nt][2] - m1);
            float p3 = __expf(sacc[nt][3] - m1);
            sacc[nt][0] = p0; sacc[nt][1] = p1;
            sacc[nt][2] = p2; sacc[nt][3] = p3;
            ls0 += p0 + p1; ls1 += p2 + p3;
        }
        l0 += ls0; l1 += ls1;

        // ---- O += P @ V (3-term split) ----
        #pragma unroll
        for (int kc = 0; kc < 8; kc++) {
            uint32_t ah[4], al[4];
            split2(sacc[2*kc][0],   sacc[2*kc][1],   ah[0], al[0]);
            split2(sacc[2*kc][2],   sacc[2*kc][3],   ah[1], al[1]);
            split2(sacc[2*kc+1][0], sacc[2*kc+1][1], ah[2], al[2]);
            split2(sacc[2*kc+1][2], sacc[2*kc+1][3], ah[3], al[3]);
            #pragma unroll
            for (int nt = 0; nt < 8; nt++) {
                const __nv_bfloat16* vr = Vth + (nt * 8 + g) * VROWP + kc * 16 + t2;
                const __nv_bfloat16* wr = Vtl + (nt * 8 + g) * VROWP + kc * 16 + t2;
                uint32_t bh[2] = { *(const uint32_t*)vr, *(const uint32_t*)(vr + 8) };
                uint32_t bl[2] = { *(const uint32_t*)wr, *(const uint32_t*)(wr + 8) };
                mma16816(oacc[nt], ah, bh);
                mma16816(oacc[nt], ah, bl);
                mma16816(oacc[nt], al, bh);
            }
        }
    }

    // ---- finalize: reduce l over quad, divide, split-store z ----
    l0 += __shfl_xor_sync(0xffffffffu, l0, 1);
    l0 += __shfl_xor_sync(0xffffffffu, l0, 2);
    l1 += __shfl_xor_sync(0xffffffffu, l1, 1);
    l1 += __shfl_xor_sync(0xffffffffu, l1, 2);
    const float inv0 = 1.f / l0, inv1 = 1.f / l1;

    const int r0 = qt * 128 + wm + g;
    const size_t zo0 = (size_t)(b * SEQ + r0) * DMODEL + h * DHEAD;
    const size_t zo1 = (size_t)(b * SEQ + r0 + 8) * DMODEL + h * DHEAD;
    #pragma unroll
    for (int nt = 0; nt < 8; nt++) {
        const int d = nt * 8 + t2;
        uint32_t zh, zl;
        split2(oacc[nt][0] * inv0, oacc[nt][1] * inv0, zh, zl);
        *(uint32_t*)(g_ahi + zo0 + d) = zh;
        *(uint32_t*)(g_alo + zo0 + d) = zl;
        split2(oacc[nt][2] * inv1, oacc[nt][3] * inv1, zh, zl);
        *(uint32_t*)(g_ahi + zo1 + d) = zh;
        *(uint32_t*)(g_alo + zo1 + d) = zl;
    }
}

// ---------------------------------------------------------------------------
// Tensor-core projection GEMM (mma.sync bf16, 3-term precision split):
//   C[M=4096, N=1024] = (Ah+Al)[M,K] @ (Bh+Bl)^T[N,K] + bias[N]
// ---------------------------------------------------------------------------
#define TK       32
#define NCHUNK   (DMODEL / TK)        // 32
#define ROWP     40                   // padded row, bf16 elems
#define MAT_BYTES (128 * ROWP * 2)    // 10240
#define STAGE_BYTES (4 * MAT_BYTES)   // 40960

__global__ __launch_bounds__(256, 1)
void gemm_tc_kernel(const float* __restrict__ bias, float* __restrict__ C)
{
    extern __shared__ __align__(16) char smem[];

    const int tid  = threadIdx.x;
    const int wid  = tid >> 5;
    const int lane = tid & 31;
    const int bm = blockIdx.y * 128;
    const int bn = blockIdx.x * 128;

    const int wm = (wid & 3) * 32;
    const int wn = (wid >> 2) * 64;

    const int g  = lane >> 2;
    const int t2 = (lane & 3) * 2;

    float acc[2][8][4];
    #pragma unroll
    for (int mt = 0; mt < 2; mt++)
        #pragma unroll
        for (int nt = 0; nt < 8; nt++)
            #pragma unroll
            for (int r = 0; r < 4; r++) acc[mt][nt][r] = 0.f;

    const int u0 = tid * 2;
    const int srow0 = u0 >> 2, scol0 = (u0 & 3) * 8;
    const int srow1 = (u0 + 1) >> 2, scol1 = ((u0 + 1) & 3) * 8;

    const __nv_bfloat16* gA[2] = { g_ahi, g_alo };
    const __nv_bfloat16* gB[2] = { g_bhi, g_blo };

    uint4 st[8];

    #pragma unroll
    for (int mx = 0; mx < 2; mx++) {
        st[mx*2+0] = *(const uint4*)(gA[mx] + (size_t)(bm + srow0) * DMODEL + scol0);
        st[mx*2+1] = *(const uint4*)(gA[mx] + (size_t)(bm + srow1) * DMODEL + scol1);
        st[4+mx*2+0] = *(const uint4*)(gB[mx] + (size_t)(bn + srow0) * DMODEL + scol0);
        st[4+mx*2+1] = *(const uint4*)(gB[mx] + (size_t)(bn + srow1) * DMODEL + scol1);
    }
    {
        char* base = smem;
        #pragma unroll
        for (int mtx = 0; mtx < 4; mtx++) {
            *(uint4*)(base + mtx*MAT_BYTES + srow0*(ROWP*2) + scol0*2) = st[mtx*2+0];
            *(uint4*)(base + mtx*MAT_BYTES + srow1*(ROWP*2) + scol1*2) = st[mtx*2+1];
        }
    }
    __syncthreads();

    for (int kc = 0; kc < NCHUNK; kc++) {
        const int cur = kc & 1;
        const bool more = (kc + 1 < NCHUNK);

        if (more) {
            const int kb = (kc + 1) * TK;
            #pragma unroll
            for (int mx = 0; mx < 2; mx++) {
                st[mx*2+0] = *(const uint4*)(gA[mx] + (size_t)(bm + srow0) * DMODEL + kb + scol0);
                st[mx*2+1] = *(const uint4*)(gA[mx] + (size_t)(bm + srow1) * DMODEL + kb + scol1);
                st[4+mx*2+0] = *(const uint4*)(gB[mx] + (size_t)(bn + srow0) * DMODEL + kb + scol0);
                st[4+mx*2+1] = *(const uint4*)(gB[mx] + (size_t)(bn + srow1) * DMODEL + kb + scol1);
            }
        }

        const __nv_bfloat16* Ah = (const __nv_bfloat16*)(smem + cur*STAGE_BYTES);
        const __nv_bfloat16* Al = (const __nv_bfloat16*)(smem + cur*STAGE_BYTES + MAT_BYTES);
        const __nv_bfloat16* Bh = (const __nv_bfloat16*)(smem + cur*STAGE_BYTES + 2*MAT_BYTES);
        const __nv_bfloat16* Bl = (const __nv_bfloat16*)(smem + cur*STAGE_BYTES + 3*MAT_BYTES);

        #pragma unroll
        for (int ks = 0; ks < 2; ks++) {
            const int k0 = ks * 16;
            uint32_t ah[2][4], al[2][4], bh[8][2], bl[8][2];
            #pragma unroll
            for (int mt = 0; mt < 2; mt++) {
                const int r0 = wm + mt * 16 + g;
                ah[mt][0] = *(const uint32_t*)&Ah[r0 * ROWP + k0 + t2];
                ah[mt][1] = *(const uint32_t*)&Ah[(r0 + 8) * ROWP + k0 + t2];
                ah[mt][2] = *(const uint32_t*)&Ah[r0 * ROWP + k0 + t2 + 8];
                ah[mt][3] = *(const uint32_t*)&Ah[(r0 + 8) * ROWP + k0 + t2 + 8];
                al[mt][0] = *(const uint32_t*)&Al[r0 * ROWP + k0 + t2];
                al[mt][1] = *(const uint32_t*)&Al[(r0 + 8) * ROWP + k0 + t2];
                al[mt][2] = *(const uint32_t*)&Al[r0 * ROWP + k0 + t2 + 8];
                al[mt][3] = *(const uint32_t*)&Al[(r0 + 8) * ROWP + k0 + t2 + 8];
            }
            #pragma unroll
            for (int nt = 0; nt < 8; nt++) {
                const int n0 = wn + nt * 8 + g;
                bh[nt][0] = *(const uint32_t*)&Bh[n0 * ROWP + k0 + t2];
                bh[nt][1] = *(const uint32_t*)&Bh[n0 * ROWP + k0 + t2 + 8];
                bl[nt][0] = *(const uint32_t*)&Bl[n0 * ROWP + k0 + t2];
                bl[nt][1] = *(const uint32_t*)&Bl[n0 * ROWP + k0 + t2 + 8];
            }
            #pragma unroll
            for (int mt = 0; mt < 2; mt++)
                #pragma unroll
                for (int nt = 0; nt < 8; nt++) {
                    mma16816(acc[mt][nt], ah[mt], bh[nt]);
                    mma16816(acc[mt][nt], ah[mt], bl[nt]);
                    mma16816(acc[mt][nt], al[mt], bh[nt]);
                }
        }

        if (more) {
            char* base = smem + (cur ^ 1) * STAGE_BYTES;
            #pragma unroll
            for (int mtx = 0; mtx < 4; mtx++) {
                *(uint4*)(base + mtx*MAT_BYTES + srow0*(ROWP*2) + scol0*2) = st[mtx*2+0];
                *(uint4*)(base + mtx*MAT_BYTES + srow1*(ROWP*2) + scol1*2) = st[mtx*2+1];
            }
            __syncthreads();
        }
    }

    #pragma unroll
    for (int mt = 0; mt < 2; mt++) {
        const int row0 = bm + wm + mt * 16 + g;
        #pragma unroll
        for (int nt = 0; nt < 8; nt++) {
            const int col0 = bn + wn + nt * 8 + t2;
            const float b0 = bias[col0], b1 = bias[col0 + 1];
            float2 o01 = { acc[mt][nt][0] + b0, acc[mt][nt][1] + b1 };
            float2 o23 = { acc[mt][nt][2] + b0, acc[mt][nt][3] + b1 };
            *(float2*)(C + (size_t)row0 * DMODEL + col0) = o01;
            *(float2*)(C + (size_t)(row0 + 8) * DMODEL + col0) = o23;
        }
    }
}

// ---------------------------------------------------------------------------
// Launch
// ---------------------------------------------------------------------------
extern "C" void kernel_launch(void* const* d_in, const int* in_sizes, int n_in,
                              void* d_out, int out_size)
{
    const float* residual = (const float*)d_in[0];
    const float* q        = (const float*)d_in[1];
    const float* k        = (const float*)d_in[2];
    const float* v        = (const float*)d_in[3];
    const float* W_O      = (const float*)d_in[4];
    const float* b_O      = (const float*)d_in[5];

    float* out = (float*)d_out;
    const int res_elems = BATCH * SEQ * DMODEL;

    const int n4 = res_elems / 4;
    copy_kernel<<<(n4 + 255) / 256, 256>>>(residual, out, n4);

    // W_O transpose + split (independent of attention)
    wsplit_kernel<<<dim3(32, 32), dim3(32, 8)>>>(W_O);

    // Tensor-core attention -> g_ahi/g_alo
    cudaFuncSetAttribute(attn_tc_kernel,
                         cudaFuncAttributeMaxDynamicSharedMemorySize, ATT_SMEM);
    attn_tc_kernel<<<dim3(SEQ / 128, NHEADS, BATCH), 256, ATT_SMEM>>>(q, k, v);

    // Tensor-core projection
    const int dyn = 2 * STAGE_BYTES;   // 80 KB
    cudaFuncSetAttribute(gemm_tc_kernel,
                         cudaFuncAttributeMaxDynamicSharedMemorySize, dyn);
    gemm_tc_kernel<<<dim3(DMODEL / 128, (BATCH * SEQ) / 128), 256, dyn>>>(
        b_O, out + res_elems);
}

// round 7
// speedup vs baseline: 3.7536x; 1.3216x over previous
#include <cuda_runtime.h>
#include <cuda_bf16.h>
#include <cstdint>

// Problem constants
#define BATCH   2
#define SEQ     2048
#define NHEADS  16
#define DHEAD   64
#define DMODEL  1024
#define ATTN_SCALE_INV 0.125f

// bf16 hi/lo split operand buffers
__device__ __nv_bfloat16 g_ahi[BATCH * SEQ * DMODEL];   // z hi  [M=4096, K=1024]
__device__ __nv_bfloat16 g_alo[BATCH * SEQ * DMODEL];   // z lo
__device__ __nv_bfloat16 g_bhi[DMODEL * DMODEL];        // W_O^T hi [N=1024, K=1024]
__device__ __nv_bfloat16 g_blo[DMODEL * DMODEL];        // W_O^T lo
// Pre-converted K: [b,h,kpos,d], V transposed: [b,h,d,kpos]
__device__ __nv_bfloat16 g_khi[BATCH * NHEADS * SEQ * DHEAD];
__device__ __nv_bfloat16 g_klo[BATCH * NHEADS * SEQ * DHEAD];
__device__ __nv_bfloat16 g_vthi[BATCH * NHEADS * DHEAD * SEQ];
__device__ __nv_bfloat16 g_vtlo[BATCH * NHEADS * DHEAD * SEQ];

// ---------------------------------------------------------------------------
// PTX helpers (portable: mma.sync sm_80, ldmatrix sm_75, cp.async sm_80)
// ---------------------------------------------------------------------------
__device__ __forceinline__ void mma16816(float* c, const uint32_t* a, const uint32_t* b)
{
    asm volatile(
        "mma.sync.aligned.m16n8k16.row.col.f32.bf16.bf16.f32 "
        "{%0,%1,%2,%3}, {%4,%5,%6,%7}, {%8,%9}, {%0,%1,%2,%3};"
        : "+f"(c[0]), "+f"(c[1]), "+f"(c[2]), "+f"(c[3])
        : "r"(a[0]), "r"(a[1]), "r"(a[2]), "r"(a[3]), "r"(b[0]), "r"(b[1]));
}

__device__ __forceinline__ void ldsm4(uint32_t* r, uint32_t addr)
{
    asm volatile("ldmatrix.sync.aligned.m8n8.x4.shared.b16 {%0,%1,%2,%3}, [%4];"
                 : "=r"(r[0]), "=r"(r[1]), "=r"(r[2]), "=r"(r[3]) : "r"(addr));
}

__device__ __forceinline__ uint32_t smem_u32(const void* p) {
    uint32_t a;
    asm("{ .reg .u64 t; cvta.to.shared.u64 t, %1; cvt.u32.u64 %0, t; }"
        : "=r"(a) : "l"(p));
    return a;
}

#define CP_ASYNC16(dst, src) \
    asm volatile("cp.async.cg.shared.global [%0], [%1], 16;" :: "r"(dst), "l"(src))
#define CP_COMMIT() asm volatile("cp.async.commit_group;" ::: "memory")
#define CP_WAIT0()  asm volatile("cp.async.wait_group 0;" ::: "memory")
#define CP_WAIT1()  asm volatile("cp.async.wait_group 1;" ::: "memory")

// Split (a,b) fp32 pair into packed bf16x2 hi + lo residual
__device__ __forceinline__ void split2(float a, float b, uint32_t& hi, uint32_t& lo)
{
    __nv_bfloat162 h2 = __floats2bfloat162_rn(a, b);
    float ra = a - __bfloat162float(h2.x);
    float rb = b - __bfloat162float(h2.y);
    __nv_bfloat162 l2 = __floats2bfloat162_rn(ra, rb);
    hi = *(uint32_t*)&h2;
    lo = *(uint32_t*)&l2;
}

// ---------------------------------------------------------------------------
// Residual passthrough
// ---------------------------------------------------------------------------
__global__ __launch_bounds__(256)
void copy_kernel(const float* __restrict__ src, float* __restrict__ dst, int n4)
{
    int i = blockIdx.x * blockDim.x + threadIdx.x;
    if (i < n4) ((float4*)dst)[i] = ((const float4*)src)[i];
}

// ---------------------------------------------------------------------------
// W_O transpose + hi/lo split: [K=1024, N=1024] -> [N, K]
// ---------------------------------------------------------------------------
__global__ __launch_bounds__(256)
void wsplit_kernel(const float* __restrict__ W)
{
    __shared__ float tile[32][33];
    const int bx = blockIdx.x * 32;
    const int by = blockIdx.y * 32;
    const int tx = threadIdx.x;
    const int ty = threadIdx.y;
    #pragma unroll
    for (int r = 0; r < 32; r += 8)
        tile[ty + r][tx] = W[(size_t)(by + ty + r) * DMODEL + bx + tx];
    __syncthreads();
    #pragma unroll
    for (int r = 0; r < 32; r += 8) {
        float f = tile[tx][ty + r];
        int n = bx + ty + r, kk = by + tx;
        __nv_bfloat16 h = __float2bfloat16(f);
        __nv_bfloat16 l = __float2bfloat16(f - __bfloat162float(h));
        g_bhi[(size_t)n * DMODEL + kk] = h;
        g_blo[(size_t)n * DMODEL + kk] = l;
    }
}

// ---------------------------------------------------------------------------
// K pre-convert: [B,S,H*D] fp32 -> [B,H,S,D] bf16 hi/lo
// ---------------------------------------------------------------------------
__global__ __launch_bounds__(256)
void ksplit_kernel(const float* __restrict__ k)
{
    int i = blockIdx.x * blockDim.x + threadIdx.x;   // over B*S*H*D/2
    if (i >= BATCH * SEQ * NHEADS * DHEAD / 2) return;
    const int d2 = i & 31;
    const int h  = (i >> 5) & 15;
    const int s  = (i >> 9) & 2047;
    const int b  = i >> 20;
    float2 f = *(const float2*)(k + ((size_t)(b * SEQ + s) * DMODEL) + h * DHEAD + d2 * 2);
    uint32_t hi, lo;
    split2(f.x, f.y, hi, lo);
    const size_t o = (((size_t)(b * NHEADS + h) * SEQ) + s) * DHEAD + d2 * 2;
    *(uint32_t*)(g_khi + o) = hi;
    *(uint32_t*)(g_klo + o) = lo;
}

// ---------------------------------------------------------------------------
// V pre-convert + transpose: [B,S,H*D] fp32 -> [B,H,D,S] bf16 hi/lo
// ---------------------------------------------------------------------------
__global__ __launch_bounds__(256)
void vtsplit_kernel(const float* __restrict__ v)
{
    __shared__ float tile[32][33];
    const int bh = blockIdx.z;                 // 0..31
    const int b  = bh >> 4, h = bh & 15;
    const int kt = blockIdx.x * 32;            // kpos base
    const int dt = blockIdx.y * 32;            // d base
    const int tx = threadIdx.x;
    const int ty = threadIdx.y;
    #pragma unroll
    for (int r = 0; r < 32; r += 8)
        tile[ty + r][tx] = v[(size_t)(b * SEQ + kt + ty + r) * DMODEL + h * DHEAD + dt + tx];
    __syncthreads();
    #pragma unroll
    for (int r = 0; r < 32; r += 8) {
        float f = tile[tx][ty + r];
        const int d = dt + ty + r, kp = kt + tx;
        __nv_bfloat16 hh = __float2bfloat16(f);
        __nv_bfloat16 ll = __float2bfloat16(f - __bfloat162float(hh));
        const size_t o = ((size_t)(bh * DHEAD + d) * SEQ) + kp;
        g_vthi[o] = hh;
        g_vtlo[o] = ll;
    }
}

// ---------------------------------------------------------------------------
// Tensor-core flash attention: cp.async 2-stage pipeline + ldmatrix frags.
// Grid: (qtile reversed, h, b). Block 256 = 8 warps x 16 q-rows.
// ---------------------------------------------------------------------------
#define KROWP 72
#define VROWP 136
// stage layout (bf16 units): Kh 0, Kl 9216, Vth 18432, Vtl 27136; total 35840
#define ST_KH  0
#define ST_KL  9216
#define ST_VTH 18432
#define ST_VTL 27136
#define STAGE_BF 35840
#define ATT_SMEM (2 * STAGE_BF * 2)   // 143360 bytes

__global__ __launch_bounds__(256, 1)
void attn_tc_kernel(const float* __restrict__ q)
{
    extern __shared__ __align__(16) char smem[];
    const uint32_t sbase = smem_u32(smem);

    const int b   = blockIdx.z;
    const int h   = blockIdx.y;
    const int bh  = b * NHEADS + h;
    const int qt  = (int)(gridDim.x - 1) - (int)blockIdx.x;
    const int tid = threadIdx.x;
    const int wid = tid >> 5;
    const int lane = tid & 31;
    const int g   = lane >> 2;
    const int t2  = (lane & 3) * 2;
    const int wm  = wid * 16;

    // cp.async source bases
    const __nv_bfloat16* kh_g = g_khi + (size_t)bh * SEQ * DHEAD;
    const __nv_bfloat16* kl_g = g_klo + (size_t)bh * SEQ * DHEAD;
    const __nv_bfloat16* vh_g = g_vthi + (size_t)bh * DHEAD * SEQ;
    const __nv_bfloat16* vl_g = g_vtlo + (size_t)bh * DHEAD * SEQ;

    // ldmatrix lane offsets (bf16 units)
    const uint32_t offK = (uint32_t)(((lane & 7) + ((lane >> 4) & 1) * 8) * KROWP
                                     + ((lane >> 3) & 1) * 8);
    const uint32_t offV = (uint32_t)(((lane & 7) + ((lane >> 4) & 1) * 8) * VROWP
                                     + ((lane >> 3) & 1) * 8);

    // ---- Q fragments (register resident, pre-scaled, hi/lo split) ----
    uint32_t qh[4][4], ql[4][4];
    {
        const float* qb = q + (size_t)b * SEQ * DMODEL + h * DHEAD;
        const int r0 = qt * 128 + wm + g;
        #pragma unroll
        for (int kc = 0; kc < 4; kc++) {
            #pragma unroll
            for (int a = 0; a < 4; a++) {
                int row = r0 + ((a & 1) ? 8 : 0);
                int col = kc * 16 + t2 + ((a >= 2) ? 8 : 0);
                float2 f = *(const float2*)(qb + (size_t)row * DMODEL + col);
                split2(f.x * ATTN_SCALE_INV, f.y * ATTN_SCALE_INV, qh[kc][a], ql[kc][a]);
            }
        }
    }

    float oacc[8][4];
    #pragma unroll
    for (int nt = 0; nt < 8; nt++)
        #pragma unroll
        for (int r = 0; r < 4; r++) oacc[nt][r] = 0.f;
    float m0 = -1e30f, m1 = -1e30f, l0 = 0.f, l1 = 0.f;

    // Tile issue: 16 x 16B per thread (K hi/lo: 8, V hi/lo: 8)
    auto issue_tile = [&](int kt, int stage) {
        const uint32_t sb = sbase + (uint32_t)stage * (STAGE_BF * 2);
        // K: 128 rows x 8 segs, 1024 ops per matrix; this thread does 4 each
        #pragma unroll
        for (int rep = 0; rep < 4; rep++) {
            int idx = tid + rep * 256;
            int row = idx >> 3, seg = idx & 7;
            const size_t go = (size_t)(kt * 128 + row) * DHEAD + seg * 8;
            uint32_t dst = sb + (uint32_t)(row * KROWP + seg * 8) * 2;
            CP_ASYNC16(dst + ST_KH * 2, kh_g + go);
            CP_ASYNC16(dst + ST_KL * 2, kl_g + go);
        }
        // V: 64 rows x 16 segs
        #pragma unroll
        for (int rep = 0; rep < 4; rep++) {
            int idx = tid + rep * 256;
            int row = idx >> 4, seg = idx & 15;
            const size_t go = (size_t)row * SEQ + kt * 128 + seg * 8;
            uint32_t dst = sb + (uint32_t)(row * VROWP + seg * 8) * 2;
            CP_ASYNC16(dst + ST_VTH * 2, vh_g + go);
            CP_ASYNC16(dst + ST_VTL * 2, vl_g + go);
        }
    };

    issue_tile(0, 0);
    CP_COMMIT();

    for (int kt = 0; kt <= qt; kt++) {
        const uint32_t sb = sbase + (uint32_t)(kt & 1) * (STAGE_BF * 2);
        const bool more = (kt < qt);
        if (more) {
            issue_tile(kt + 1, (kt + 1) & 1);
            CP_COMMIT();
            CP_WAIT1();
        } else {
            CP_WAIT0();
        }
        __syncthreads();

        // ---- S = Q @ K^T (3-term split, ldmatrix frags) ----
        float sacc[16][4];
        #pragma unroll
        for (int ntp = 0; ntp < 8; ntp++) {
            sacc[2*ntp][0] = sacc[2*ntp][1] = sacc[2*ntp][2] = sacc[2*ntp][3] = 0.f;
            sacc[2*ntp+1][0] = sacc[2*ntp+1][1] = sacc[2*ntp+1][2] = sacc[2*ntp+1][3] = 0.f;
            #pragma unroll
            for (int kc = 0; kc < 4; kc++) {
                const uint32_t rel = (uint32_t)(ntp * 16 * KROWP + kc * 16 + offK) * 2;
                uint32_t bh2[4], bl2[4];
                ldsm4(bh2, sb + ST_KH * 2 + rel);
                ldsm4(bl2, sb + ST_KL * 2 + rel);
                mma16816(sacc[2*ntp],   qh[kc], bh2);
                mma16816(sacc[2*ntp],   qh[kc], bl2);
                mma16816(sacc[2*ntp],   ql[kc], bh2);
                mma16816(sacc[2*ntp+1], qh[kc], bh2 + 2);
                mma16816(sacc[2*ntp+1], qh[kc], bl2 + 2);
                mma16816(sacc[2*ntp+1], ql[kc], bh2 + 2);
            }
        }

        // ---- causal mask (diagonal tile only) ----
        if (kt == qt) {
            const int rl0 = wm + g, rl1 = rl0 + 8;
            #pragma unroll
            for (int nt = 0; nt < 16; nt++) {
                int c0 = nt * 8 + t2;
                if (c0     > rl0) sacc[nt][0] = -1e30f;
                if (c0 + 1 > rl0) sacc[nt][1] = -1e30f;
                if (c0     > rl1) sacc[nt][2] = -1e30f;
                if (c0 + 1 > rl1) sacc[nt][3] = -1e30f;
            }
        }

        // ---- online softmax ----
        float mx0 = -1e30f, mx1 = -1e30f;
        #pragma unroll
        for (int nt = 0; nt < 16; nt++) {
            mx0 = fmaxf(mx0, fmaxf(sacc[nt][0], sacc[nt][1]));
            mx1 = fmaxf(mx1, fmaxf(sacc[nt][2], sacc[nt][3]));
        }
        mx0 = fmaxf(mx0, __shfl_xor_sync(0xffffffffu, mx0, 1));
        mx0 = fmaxf(mx0, __shfl_xor_sync(0xffffffffu, mx0, 2));
        mx1 = fmaxf(mx1, __shfl_xor_sync(0xffffffffu, mx1, 1));
        mx1 = fmaxf(mx1, __shfl_xor_sync(0xffffffffu, mx1, 2));

        float mn0 = fmaxf(m0, mx0), mn1 = fmaxf(m1, mx1);
        float c0 = __expf(m0 - mn0), c1 = __expf(m1 - mn1);
        m0 = mn0; m1 = mn1;
        l0 *= c0; l1 *= c1;
        #pragma unroll
        for (int nt = 0; nt < 8; nt++) {
            oacc[nt][0] *= c0; oacc[nt][1] *= c0;
            oacc[nt][2] *= c1; oacc[nt][3] *= c1;
        }

        float ls0 = 0.f, ls1 = 0.f;
        #pragma unroll
        for (int nt = 0; nt < 16; nt++) {
            float p0 = __expf(sacc[nt][0] - m0);
            float p1 = __expf(sacc[nt][1] - m0);
            float p2 = __expf(sacc[nt][2] - m1);
            float p3 = __expf(sacc[nt][3] - m1);
            sacc[nt][0] = p0; sacc[nt][1] = p1;
            sacc[nt][2] = p2; sacc[nt][3] = p3;
            ls0 += p0 + p1; ls1 += p2 + p3;
        }
        l0 += ls0; l1 += ls1;

        // ---- O += P @ V (3-term split, ldmatrix frags) ----
        #pragma unroll
        for (int kc = 0; kc < 8; kc++) {
            uint32_t ah[4], al[4];
            split2(sacc[2*kc][0],   sacc[2*kc][1],   ah[0], al[0]);
            split2(sacc[2*kc][2],   sacc[2*kc][3],   ah[1], al[1]);
            split2(sacc[2*kc+1][0], sacc[2*kc+1][1], ah[2], al[2]);
            split2(sacc[2*kc+1][2], sacc[2*kc+1][3], ah[3], al[3]);
            #pragma unroll
            for (int ntp = 0; ntp < 4; ntp++) {
                const uint32_t rel = (uint32_t)(ntp * 16 * VROWP + kc * 16 + offV) * 2;
                uint32_t bh2[4], bl2[4];
                ldsm4(bh2, sb + ST_VTH * 2 + rel);
                ldsm4(bl2, sb + ST_VTL * 2 + rel);
                mma16816(oacc[2*ntp],   ah, bh2);
                mma16816(oacc[2*ntp],   ah, bl2);
                mma16816(oacc[2*ntp],   al, bh2);
                mma16816(oacc[2*ntp+1], ah, bh2 + 2);
                mma16816(oacc[2*ntp+1], ah, bl2 + 2);
                mma16816(oacc[2*ntp+1], al, bh2 + 2);
            }
        }
        __syncthreads();
    }

    // ---- finalize ----
    l0 += __shfl_xor_sync(0xffffffffu, l0, 1);
    l0 += __shfl_xor_sync(0xffffffffu, l0, 2);
    l1 += __shfl_xor_sync(0xffffffffu, l1, 1);
    l1 += __shfl_xor_sync(0xffffffffu, l1, 2);
    const float inv0 = 1.f / l0, inv1 = 1.f / l1;

    const int r0 = qt * 128 + wm + g;
    const size_t zo0 = (size_t)(b * SEQ + r0) * DMODEL + h * DHEAD;
    const size_t zo1 = (size_t)(b * SEQ + r0 + 8) * DMODEL + h * DHEAD;
    #pragma unroll
    for (int nt = 0; nt < 8; nt++) {
        const int d = nt * 8 + t2;
        uint32_t zh, zl;
        split2(oacc[nt][0] * inv0, oacc[nt][1] * inv0, zh, zl);
        *(uint32_t*)(g_ahi + zo0 + d) = zh;
        *(uint32_t*)(g_alo + zo0 + d) = zl;
        split2(oacc[nt][2] * inv1, oacc[nt][3] * inv1, zh, zl);
        *(uint32_t*)(g_ahi + zo1 + d) = zh;
        *(uint32_t*)(g_alo + zo1 + d) = zl;
    }
}

// ---------------------------------------------------------------------------
// Tensor-core projection GEMM (mma.sync + ldmatrix, 3-term split)
// ---------------------------------------------------------------------------
#define TK       32
#define NCHUNK   (DMODEL / TK)        // 32
#define ROWP     40                   // padded row, bf16 elems
#define MAT_BYTES (128 * ROWP * 2)    // 10240
#define GSTAGE_BYTES (4 * MAT_BYTES)  // 40960

__global__ __launch_bounds__(256, 1)
void gemm_tc_kernel(const float* __restrict__ bias, float* __restrict__ C)
{
    extern __shared__ __align__(16) char smem[];
    const uint32_t sbase = smem_u32(smem);

    const int tid  = threadIdx.x;
    const int wid  = tid >> 5;
    const int lane = tid & 31;
    const int bm = blockIdx.y * 128;
    const int bn = blockIdx.x * 128;

    const int wm = (wid & 3) * 32;
    const int wn = (wid >> 2) * 64;

    const int g  = lane >> 2;
    const int t2 = (lane & 3) * 2;

    // ldmatrix lane offsets (bf16 units)
    const uint32_t offA = (uint32_t)(((lane & 7) + ((lane >> 3) & 1) * 8) * ROWP
                                     + ((lane >> 4) & 1) * 8);
    const uint32_t offB = (uint32_t)(((lane & 7) + ((lane >> 4) & 1) * 8) * ROWP
                                     + ((lane >> 3) & 1) * 8);

    float acc[2][8][4];
    #pragma unroll
    for (int mt = 0; mt < 2; mt++)
        #pragma unroll
        for (int nt = 0; nt < 8; nt++)
            #pragma unroll
            for (int r = 0; r < 4; r++) acc[mt][nt][r] = 0.f;

    const int u0 = tid * 2;
    const int srow0 = u0 >> 2, scol0 = (u0 & 3) * 8;
    const int srow1 = (u0 + 1) >> 2, scol1 = ((u0 + 1) & 3) * 8;

    const __nv_bfloat16* gA[2] = { g_ahi, g_alo };
    const __nv_bfloat16* gB[2] = { g_bhi, g_blo };

    uint4 st[8];

    #pragma unroll
    for (int mx = 0; mx < 2; mx++) {
        st[mx*2+0] = *(const uint4*)(gA[mx] + (size_t)(bm + srow0) * DMODEL + scol0);
        st[mx*2+1] = *(const uint4*)(gA[mx] + (size_t)(bm + srow1) * DMODEL + scol1);
        st[4+mx*2+0] = *(const uint4*)(gB[mx] + (size_t)(bn + srow0) * DMODEL + scol0);
        st[4+mx*2+1] = *(const uint4*)(gB[mx] + (size_t)(bn + srow1) * DMODEL + scol1);
    }
    {
        char* base = smem;
        #pragma unroll
        for (int mtx = 0; mtx < 4; mtx++) {
            *(uint4*)(base + mtx*MAT_BYTES + srow0*(ROWP*2) + scol0*2) = st[mtx*2+0];
            *(uint4*)(base + mtx*MAT_BYTES + srow1*(ROWP*2) + scol1*2) = st[mtx*2+1];
        }
    }
    __syncthreads();

    for (int kc = 0; kc < NCHUNK; kc++) {
        const int cur = kc & 1;
        const bool more = (kc + 1 < NCHUNK);

        if (more) {
            const int kb = (kc + 1) * TK;
            #pragma unroll
            for (int mx = 0; mx < 2; mx++) {
                st[mx*2+0] = *(const uint4*)(gA[mx] + (size_t)(bm + srow0) * DMODEL + kb + scol0);
                st[mx*2+1] = *(const uint4*)(gA[mx] + (size_t)(bm + srow1) * DMODEL + kb + scol1);
                st[4+mx*2+0] = *(const uint4*)(gB[mx] + (size_t)(bn + srow0) * DMODEL + kb + scol0);
                st[4+mx*2+1] = *(const uint4*)(gB[mx] + (size_t)(bn + srow1) * DMODEL + kb + scol1);
            }
        }

        const uint32_t sAh = sbase + (uint32_t)cur * GSTAGE_BYTES;
        const uint32_t sAl = sAh + MAT_BYTES;
        const uint32_t sBh = sAh + 2 * MAT_BYTES;
        const uint32_t sBl = sAh + 3 * MAT_BYTES;

        #pragma unroll
        for (int ks = 0; ks < 2; ks++) {
            const int k0 = ks * 16;
            uint32_t ah[2][4], al[2][4];
            #pragma unroll
            for (int mt = 0; mt < 2; mt++) {
                const uint32_t rel = (uint32_t)((wm + mt * 16) * ROWP + k0 + offA) * 2;
                ldsm4(ah[mt], sAh + rel);
                ldsm4(al[mt], sAl + rel);
            }
            #pragma unroll
            for (int ntp = 0; ntp < 4; ntp++) {
                const uint32_t rel = (uint32_t)((wn + ntp * 16) * ROWP + k0 + offB) * 2;
                uint32_t bh2[4], bl2[4];
                ldsm4(bh2, sBh + rel);
                ldsm4(bl2, sBl + rel);
                #pragma unroll
                for (int mt = 0; mt < 2; mt++) {
                    mma16816(acc[mt][2*ntp],   ah[mt], bh2);
                    mma16816(acc[mt][2*ntp],   ah[mt], bl2);
                    mma16816(acc[mt][2*ntp],   al[mt], bh2);
                    mma16816(acc[mt][2*ntp+1], ah[mt], bh2 + 2);
                    mma16816(acc[mt][2*ntp+1], ah[mt], bl2 + 2);
                    mma16816(acc[mt][2*ntp+1], al[mt], bh2 + 2);
                }
            }
        }

        if (more) {
            char* base = smem + (cur ^ 1) * GSTAGE_BYTES;
            #pragma unroll
            for (int mtx = 0; mtx < 4; mtx++) {
                *(uint4*)(base + mtx*MAT_BYTES + srow0*(ROWP*2) + scol0*2) = st[mtx*2+0];
                *(uint4*)(base + mtx*MAT_BYTES + srow1*(ROWP*2) + scol1*2) = st[mtx*2+1];
            }
            __syncthreads();
        }
    }

    #pragma unroll
    for (int mt = 0; mt < 2; mt++) {
        const int row0 = bm + wm + mt * 16 + g;
        #pragma unroll
        for (int nt = 0; nt < 8; nt++) {
            const int col0 = bn + wn + nt * 8 + t2;
            const float b0 = bias[col0], b1 = bias[col0 + 1];
            float2 o01 = { acc[mt][nt][0] + b0, acc[mt][nt][1] + b1 };
            float2 o23 = { acc[mt][nt][2] + b0, acc[mt][nt][3] + b1 };
            *(float2*)(C + (size_t)row0 * DMODEL + col0) = o01;
            *(float2*)(C + (size_t)(row0 + 8) * DMODEL + col0) = o23;
        }
    }
}

// ---------------------------------------------------------------------------
// Launch
// ---------------------------------------------------------------------------
extern "C" void kernel_launch(void* const* d_in, const int* in_sizes, int n_in,
                              void* d_out, int out_size)
{
    const float* residual = (const float*)d_in[0];
    const float* q        = (const float*)d_in[1];
    const float* k        = (const float*)d_in[2];
    const float* v        = (const float*)d_in[3];
    const float* W_O      = (const float*)d_in[4];
    const float* b_O      = (const float*)d_in[5];

    float* out = (float*)d_out;
    const int res_elems = BATCH * SEQ * DMODEL;

    const int n4 = res_elems / 4;
    copy_kernel<<<(n4 + 255) / 256, 256>>>(residual, out, n4);

    // Operand pre-conversion (independent kernels)
    wsplit_kernel<<<dim3(32, 32), dim3(32, 8)>>>(W_O);
    const int kn = BATCH * SEQ * NHEADS * DHEAD / 2;
    ksplit_kernel<<<(kn + 255) / 256, 256>>>(k);
    vtsplit_kernel<<<dim3(SEQ / 32, DHEAD / 32, BATCH * NHEADS), dim3(32, 8)>>>(v);

    // Tensor-core attention -> g_ahi/g_alo
    cudaFuncSetAttribute(attn_tc_kernel,
                         cudaFuncAttributeMaxDynamicSharedMemorySize, ATT_SMEM);
    attn_tc_kernel<<<dim3(SEQ / 128, NHEADS, BATCH), 256, ATT_SMEM>>>(q);

    // Tensor-core projection
    const int dyn = 2 * GSTAGE_BYTES;   // 80 KB
    cudaFuncSetAttribute(gemm_tc_kernel,
                         cudaFuncAttributeMaxDynamicSharedMemorySize, dyn);
    gemm_tc_kernel<<<dim3(DMODEL / 128, (BATCH * SEQ) / 128), 256, dyn>>>(
        b_O, out + res_elems);
}

// round 8
// speedup vs baseline: 3.7893x; 1.0095x over previous
#include <cuda_runtime.h>
#include <cuda_bf16.h>
#include <cstdint>

// Problem constants
#define BATCH   2
#define SEQ     2048
#define NHEADS  16
#define DHEAD   64
#define DMODEL  1024
#define ATTN_SCALE_INV 0.125f
#define LOG2E 1.4426950408889634f

// bf16 hi/lo split operand buffers
__device__ __nv_bfloat16 g_ahi[BATCH * SEQ * DMODEL];   // z hi  [M=4096, K=1024]
__device__ __nv_bfloat16 g_alo[BATCH * SEQ * DMODEL];   // z lo
__device__ __nv_bfloat16 g_bhi[DMODEL * DMODEL];        // W_O^T hi [N=1024, K=1024]
__device__ __nv_bfloat16 g_blo[DMODEL * DMODEL];        // W_O^T lo
// Pre-converted K: [b,h,kpos,d], V transposed: [b,h,d,kpos]
__device__ __nv_bfloat16 g_khi[BATCH * NHEADS * SEQ * DHEAD];
__device__ __nv_bfloat16 g_klo[BATCH * NHEADS * SEQ * DHEAD];
__device__ __nv_bfloat16 g_vthi[BATCH * NHEADS * DHEAD * SEQ];
__device__ __nv_bfloat16 g_vtlo[BATCH * NHEADS * DHEAD * SEQ];

// ---------------------------------------------------------------------------
// PTX helpers (portable: mma.sync sm_80, ldmatrix sm_75, cp.async sm_80)
// ---------------------------------------------------------------------------
__device__ __forceinline__ void mma16816(float* c, const uint32_t* a, const uint32_t* b)
{
    asm volatile(
        "mma.sync.aligned.m16n8k16.row.col.f32.bf16.bf16.f32 "
        "{%0,%1,%2,%3}, {%4,%5,%6,%7}, {%8,%9}, {%0,%1,%2,%3};"
        : "+f"(c[0]), "+f"(c[1]), "+f"(c[2]), "+f"(c[3])
        : "r"(a[0]), "r"(a[1]), "r"(a[2]), "r"(a[3]), "r"(b[0]), "r"(b[1]));
}

__device__ __forceinline__ void ldsm4(uint32_t* r, uint32_t addr)
{
    asm volatile("ldmatrix.sync.aligned.m8n8.x4.shared.b16 {%0,%1,%2,%3}, [%4];"
                 : "=r"(r[0]), "=r"(r[1]), "=r"(r[2]), "=r"(r[3]) : "r"(addr));
}

__device__ __forceinline__ uint32_t smem_u32(const void* p) {
    uint32_t a;
    asm("{ .reg .u64 t; cvta.to.shared.u64 t, %1; cvt.u32.u64 %0, t; }"
        : "=r"(a) : "l"(p));
    return a;
}

__device__ __forceinline__ float ex2(float x) {
    float r;
    asm("ex2.approx.f32 %0, %1;" : "=f"(r) : "f"(x));
    return r;
}

#define CP_ASYNC16(dst, src) \
    asm volatile("cp.async.cg.shared.global [%0], [%1], 16;" :: "r"(dst), "l"(src))
#define CP_COMMIT() asm volatile("cp.async.commit_group;" ::: "memory")
#define CP_WAIT1()  asm volatile("cp.async.wait_group 1;" ::: "memory")

// Split (a,b) fp32 pair into packed bf16x2 hi + lo residual
__device__ __forceinline__ void split2(float a, float b, uint32_t& hi, uint32_t& lo)
{
    __nv_bfloat162 h2 = __floats2bfloat162_rn(a, b);
    float ra = a - __bfloat162float(h2.x);
    float rb = b - __bfloat162float(h2.y);
    __nv_bfloat162 l2 = __floats2bfloat162_rn(ra, rb);
    hi = *(uint32_t*)&h2;
    lo = *(uint32_t*)&l2;
}

// ---------------------------------------------------------------------------
// Residual passthrough
// ---------------------------------------------------------------------------
__global__ __launch_bounds__(256)
void copy_kernel(const float* __restrict__ src, float* __restrict__ dst, int n4)
{
    int i = blockIdx.x * blockDim.x + threadIdx.x;
    if (i < n4) ((float4*)dst)[i] = ((const float4*)src)[i];
}

// ---------------------------------------------------------------------------
// W_O transpose + hi/lo split: [K=1024, N=1024] -> [N, K]
// ---------------------------------------------------------------------------
__global__ __launch_bounds__(256)
void wsplit_kernel(const float* __restrict__ W)
{
    __shared__ float tile[32][33];
    const int bx = blockIdx.x * 32;
    const int by = blockIdx.y * 32;
    const int tx = threadIdx.x;
    const int ty = threadIdx.y;
    #pragma unroll
    for (int r = 0; r < 32; r += 8)
        tile[ty + r][tx] = W[(size_t)(by + ty + r) * DMODEL + bx + tx];
    __syncthreads();
    #pragma unroll
    for (int r = 0; r < 32; r += 8) {
        float f = tile[tx][ty + r];
        int n = bx + ty + r, kk = by + tx;
        __nv_bfloat16 h = __float2bfloat16(f);
        __nv_bfloat16 l = __float2bfloat16(f - __bfloat162float(h));
        g_bhi[(size_t)n * DMODEL + kk] = h;
        g_blo[(size_t)n * DMODEL + kk] = l;
    }
}

// ---------------------------------------------------------------------------
// K pre-convert: [B,S,H*D] fp32 -> [B,H,S,D] bf16 hi/lo
// ---------------------------------------------------------------------------
__global__ __launch_bounds__(256)
void ksplit_kernel(const float* __restrict__ k)
{
    int i = blockIdx.x * blockDim.x + threadIdx.x;
    if (i >= BATCH * SEQ * NHEADS * DHEAD / 2) return;
    const int d2 = i & 31;
    const int h  = (i >> 5) & 15;
    const int s  = (i >> 9) & 2047;
    const int b  = i >> 20;
    float2 f = *(const float2*)(k + ((size_t)(b * SEQ + s) * DMODEL) + h * DHEAD + d2 * 2);
    uint32_t hi, lo;
    split2(f.x, f.y, hi, lo);
    const size_t o = (((size_t)(b * NHEADS + h) * SEQ) + s) * DHEAD + d2 * 2;
    *(uint32_t*)(g_khi + o) = hi;
    *(uint32_t*)(g_klo + o) = lo;
}

// ---------------------------------------------------------------------------
// V pre-convert + transpose: [B,S,H*D] fp32 -> [B,H,D,S] bf16 hi/lo
// ---------------------------------------------------------------------------
__global__ __launch_bounds__(256)
void vtsplit_kernel(const float* __restrict__ v)
{
    __shared__ float tile[32][33];
    const int bh = blockIdx.z;
    const int b  = bh >> 4, h = bh & 15;
    const int kt = blockIdx.x * 32;
    const int dt = blockIdx.y * 32;
    const int tx = threadIdx.x;
    const int ty = threadIdx.y;
    #pragma unroll
    for (int r = 0; r < 32; r += 8)
        tile[ty + r][tx] = v[(size_t)(b * SEQ + kt + ty + r) * DMODEL + h * DHEAD + dt + tx];
    __syncthreads();
    #pragma unroll
    for (int r = 0; r < 32; r += 8) {
        float f = tile[tx][ty + r];
        const int d = dt + ty + r, kp = kt + tx;
        __nv_bfloat16 hh = __float2bfloat16(f);
        __nv_bfloat16 ll = __float2bfloat16(f - __bfloat162float(hh));
        const size_t o = ((size_t)(bh * DHEAD + d) * SEQ) + kp;
        g_vthi[o] = hh;
        g_vtlo[o] = ll;
    }
}

// ---------------------------------------------------------------------------
// Tensor-core flash attention: 3-stage cp.async pipeline, ldmatrix frags,
// softmax in log2 domain. Grid: (qtile reversed, h, b). 8 warps x 16 q-rows.
// ---------------------------------------------------------------------------
#define KROWP 72
#define VROWP 136
#define ST_KH  0
#define ST_KL  9216
#define ST_VTH 18432
#define ST_VTL 27136
#define STAGE_BF 35840
#define ATT_SMEM (3 * STAGE_BF * 2)   // 215040 bytes

__global__ __launch_bounds__(256, 1)
void attn_tc_kernel(const float* __restrict__ q)
{
    extern __shared__ __align__(16) char smem[];
    const uint32_t sbase = smem_u32(smem);

    const int b   = blockIdx.z;
    const int h   = blockIdx.y;
    const int bh  = b * NHEADS + h;
    const int qt  = (int)(gridDim.x - 1) - (int)blockIdx.x;
    const int tid = threadIdx.x;
    const int wid = tid >> 5;
    const int lane = tid & 31;
    const int g   = lane >> 2;
    const int t2  = (lane & 3) * 2;
    const int wm  = wid * 16;

    const __nv_bfloat16* kh_g = g_khi + (size_t)bh * SEQ * DHEAD;
    const __nv_bfloat16* kl_g = g_klo + (size_t)bh * SEQ * DHEAD;
    const __nv_bfloat16* vh_g = g_vthi + (size_t)bh * DHEAD * SEQ;
    const __nv_bfloat16* vl_g = g_vtlo + (size_t)bh * DHEAD * SEQ;

    const uint32_t offK = (uint32_t)(((lane & 7) + ((lane >> 4) & 1) * 8) * KROWP
                                     + ((lane >> 3) & 1) * 8);
    const uint32_t offV = (uint32_t)(((lane & 7) + ((lane >> 4) & 1) * 8) * VROWP
                                     + ((lane >> 3) & 1) * 8);

    // ---- Q fragments (pre-scaled by 1/sqrt(d) * log2(e), hi/lo split) ----
    uint32_t qh[4][4], ql[4][4];
    {
        const float qsc = ATTN_SCALE_INV * LOG2E;
        const float* qb = q + (size_t)b * SEQ * DMODEL + h * DHEAD;
        const int r0 = qt * 128 + wm + g;
        #pragma unroll
        for (int kc = 0; kc < 4; kc++) {
            #pragma unroll
            for (int a = 0; a < 4; a++) {
                int row = r0 + ((a & 1) ? 8 : 0);
                int col = kc * 16 + t2 + ((a >= 2) ? 8 : 0);
                float2 f = *(const float2*)(qb + (size_t)row * DMODEL + col);
                split2(f.x * qsc, f.y * qsc, qh[kc][a], ql[kc][a]);
            }
        }
    }

    float oacc[8][4];
    #pragma unroll
    for (int nt = 0; nt < 8; nt++)
        #pragma unroll
        for (int r = 0; r < 4; r++) oacc[nt][r] = 0.f;
    float m0 = -1e30f, m1 = -1e30f, l0 = 0.f, l1 = 0.f;

    auto issue_tile = [&](int tt, int stage) {
        const uint32_t sb = sbase + (uint32_t)stage * (STAGE_BF * 2);
        #pragma unroll
        for (int rep = 0; rep < 4; rep++) {
            int idx = tid + rep * 256;
            int row = idx >> 3, seg = idx & 7;
            const size_t go = (size_t)(tt * 128 + row) * DHEAD + seg * 8;
            uint32_t dst = sb + (uint32_t)(row * KROWP + seg * 8) * 2;
            CP_ASYNC16(dst + ST_KH * 2, kh_g + go);
            CP_ASYNC16(dst + ST_KL * 2, kl_g + go);
        }
        #pragma unroll
        for (int rep = 0; rep < 4; rep++) {
            int idx = tid + rep * 256;
            int row = idx >> 4, seg = idx & 15;
            const size_t go = (size_t)row * SEQ + tt * 128 + seg * 8;
            uint32_t dst = sb + (uint32_t)(row * VROWP + seg * 8) * 2;
            CP_ASYNC16(dst + ST_VTH * 2, vh_g + go);
            CP_ASYNC16(dst + ST_VTL * 2, vl_g + go);
        }
    };

    // Prologue: stages 0 and 1 in flight (empty group if qt == 0)
    issue_tile(0, 0);
    CP_COMMIT();
    if (qt >= 1) issue_tile(1, 1);
    CP_COMMIT();

    for (int kt = 0; kt <= qt; kt++) {
        const uint32_t sb = sbase + (uint32_t)(kt % 3) * (STAGE_BF * 2);
        CP_WAIT1();          // group kt complete (one newer may pend)
        __syncthreads();     // visibility + ends compute of kt-1 for all warps

        // ---- S = Q @ K^T (3-term split, ldmatrix frags) ----
        float sacc[16][4];
        #pragma unroll
        for (int ntp = 0; ntp < 8; ntp++) {
            sacc[2*ntp][0] = sacc[2*ntp][1] = sacc[2*ntp][2] = sacc[2*ntp][3] = 0.f;
            sacc[2*ntp+1][0] = sacc[2*ntp+1][1] = sacc[2*ntp+1][2] = sacc[2*ntp+1][3] = 0.f;
            #pragma unroll
            for (int kc = 0; kc < 4; kc++) {
                const uint32_t rel = (uint32_t)(ntp * 16 * KROWP + kc * 16 + offK) * 2;
                uint32_t bh2[4], bl2[4];
                ldsm4(bh2, sb + ST_KH * 2 + rel);
                ldsm4(bl2, sb + ST_KL * 2 + rel);
                mma16816(sacc[2*ntp],   qh[kc], bh2);
                mma16816(sacc[2*ntp],   qh[kc], bl2);
                mma16816(sacc[2*ntp],   ql[kc], bh2);
                mma16816(sacc[2*ntp+1], qh[kc], bh2 + 2);
                mma16816(sacc[2*ntp+1], qh[kc], bl2 + 2);
                mma16816(sacc[2*ntp+1], ql[kc], bh2 + 2);
            }
        }

        // ---- causal mask (diagonal tile only) ----
        if (kt == qt) {
            const int rl0 = wm + g, rl1 = rl0 + 8;
            #pragma unroll
            for (int nt = 0; nt < 16; nt++) {
                int c0 = nt * 8 + t2;
                if (c0     > rl0) sacc[nt][0] = -1e30f;
                if (c0 + 1 > rl0) sacc[nt][1] = -1e30f;
                if (c0     > rl1) sacc[nt][2] = -1e30f;
                if (c0 + 1 > rl1) sacc[nt][3] = -1e30f;
            }
        }

        // ---- online softmax (log2 domain) ----
        float mx0 = -1e30f, mx1 = -1e30f;
        #pragma unroll
        for (int nt = 0; nt < 16; nt++) {
            mx0 = fmaxf(mx0, fmaxf(sacc[nt][0], sacc[nt][1]));
            mx1 = fmaxf(mx1, fmaxf(sacc[nt][2], sacc[nt][3]));
        }
        mx0 = fmaxf(mx0, __shfl_xor_sync(0xffffffffu, mx0, 1));
        mx0 = fmaxf(mx0, __shfl_xor_sync(0xffffffffu, mx0, 2));
        mx1 = fmaxf(mx1, __shfl_xor_sync(0xffffffffu, mx1, 1));
        mx1 = fmaxf(mx1, __shfl_xor_sync(0xffffffffu, mx1, 2));

        float mn0 = fmaxf(m0, mx0), mn1 = fmaxf(m1, mx1);
        float c0 = ex2(m0 - mn0), c1 = ex2(m1 - mn1);
        m0 = mn0; m1 = mn1;
        l0 *= c0; l1 *= c1;
        #pragma unroll
        for (int nt = 0; nt < 8; nt++) {
            oacc[nt][0] *= c0; oacc[nt][1] *= c0;
            oacc[nt][2] *= c1; oacc[nt][3] *= c1;
        }

        float ls0 = 0.f, ls1 = 0.f;
        #pragma unroll
        for (int nt = 0; nt < 16; nt++) {
            float p0 = ex2(sacc[nt][0] - m0);
            float p1 = ex2(sacc[nt][1] - m0);
            float p2 = ex2(sacc[nt][2] - m1);
            float p3 = ex2(sacc[nt][3] - m1);
            sacc[nt][0] = p0; sacc[nt][1] = p1;
            sacc[nt][2] = p2; sacc[nt][3] = p3;
            ls0 += p0 + p1; ls1 += p2 + p3;
        }
        l0 += ls0; l1 += ls1;

        // ---- O += P @ V (3-term split, ldmatrix frags) ----
        #pragma unroll
        for (int kc = 0; kc < 8; kc++) {
            uint32_t ah[4], al[4];
            split2(sacc[2*kc][0],   sacc[2*kc][1],   ah[0], al[0]);
            split2(sacc[2*kc][2],   sacc[2*kc][3],   ah[1], al[1]);
            split2(sacc[2*kc+1][0], sacc[2*kc+1][1], ah[2], al[2]);
            split2(sacc[2*kc+1][2], sacc[2*kc+1][3], ah[3], al[3]);
            #pragma unroll
            for (int ntp = 0; ntp < 4; ntp++) {
                const uint32_t rel = (uint32_t)(ntp * 16 * VROWP + kc * 16 + offV) * 2;
                uint32_t bh2[4], bl2[4];
                ldsm4(bh2, sb + ST_VTH * 2 + rel);
                ldsm4(bl2, sb + ST_VTL * 2 + rel);
                mma16816(oacc[2*ntp],   ah, bh2);
                mma16816(oacc[2*ntp],   ah, bl2);
                mma16816(oacc[2*ntp],   al, bh2);
                mma16816(oacc[2*ntp+1], ah, bh2 + 2);
                mma16816(oacc[2*ntp+1], ah, bl2 + 2);
                mma16816(oacc[2*ntp+1], al, bh2 + 2);
            }
        }

        // ---- issue tile kt+2 into stage (kt+2)%3 (consumed at kt-1, safe) ----
        if (kt + 2 <= qt) issue_tile(kt + 2, (kt + 2) % 3);
        CP_COMMIT();
    }

    // ---- finalize ----
    l0 += __shfl_xor_sync(0xffffffffu, l0, 1);
    l0 += __shfl_xor_sync(0xffffffffu, l0, 2);
    l1 += __shfl_xor_sync(0xffffffffu, l1, 1);
    l1 += __shfl_xor_sync(0xffffffffu, l1, 2);
    const float inv0 = 1.f / l0, inv1 = 1.f / l1;

    const int r0 = qt * 128 + wm + g;
    const size_t zo0 = (size_t)(b * SEQ + r0) * DMODEL + h * DHEAD;
    const size_t zo1 = (size_t)(b * SEQ + r0 + 8) * DMODEL + h * DHEAD;
    #pragma unroll
    for (int nt = 0; nt < 8; nt++) {
        const int d = nt * 8 + t2;
        uint32_t zh, zl;
        split2(oacc[nt][0] * inv0, oacc[nt][1] * inv0, zh, zl);
        *(uint32_t*)(g_ahi + zo0 + d) = zh;
        *(uint32_t*)(g_alo + zo0 + d) = zl;
        split2(oacc[nt][2] * inv1, oacc[nt][3] * inv1, zh, zl);
        *(uint32_t*)(g_ahi + zo1 + d) = zh;
        *(uint32_t*)(g_alo + zo1 + d) = zl;
    }
}

// ---------------------------------------------------------------------------
// Tensor-core projection GEMM: 3-stage cp.async pipeline + ldmatrix,
// 3-term precision split. C[4096,1024] = (Ah+Al)@(Bh+Bl)^T + bias.
// ---------------------------------------------------------------------------
#define TK       32
#define NCHUNK   (DMODEL / TK)        // 32
#define ROWP     40                   // padded row, bf16 elems (80B)
#define MAT_BYTES (128 * ROWP * 2)    // 10240
#define GSTAGE_BYTES (4 * MAT_BYTES)  // 40960
#define GEMM_SMEM (3 * GSTAGE_BYTES)  // 122880

__global__ __launch_bounds__(256, 1)
void gemm_tc_kernel(const float* __restrict__ bias, float* __restrict__ C)
{
    extern __shared__ __align__(16) char smem[];
    const uint32_t sbase = smem_u32(smem);

    const int tid  = threadIdx.x;
    const int wid  = tid >> 5;
    const int lane = tid & 31;
    const int bm = blockIdx.y * 128;
    const int bn = blockIdx.x * 128;

    const int wm = (wid & 3) * 32;
    const int wn = (wid >> 2) * 64;

    const int g  = lane >> 2;
    const int t2 = (lane & 3) * 2;

    const uint32_t offA = (uint32_t)(((lane & 7) + ((lane >> 3) & 1) * 8) * ROWP
                                     + ((lane >> 4) & 1) * 8);
    const uint32_t offB = (uint32_t)(((lane & 7) + ((lane >> 4) & 1) * 8) * ROWP
                                     + ((lane >> 3) & 1) * 8);

    float acc[2][8][4];
    #pragma unroll
    for (int mt = 0; mt < 2; mt++)
        #pragma unroll
        for (int nt = 0; nt < 8; nt++)
            #pragma unroll
            for (int r = 0; r < 4; r++) acc[mt][nt][r] = 0.f;

    auto issue_chunk = [&](int kc, int stage) {
        const uint32_t sb = sbase + (uint32_t)stage * GSTAGE_BYTES;
        const int kb = kc * TK;
        #pragma unroll
        for (int rep = 0; rep < 2; rep++) {
            int gi = tid * 2 + rep;              // 0..511
            int row = gi >> 2, seg = gi & 3;
            uint32_t d = sb + (uint32_t)(row * (ROWP * 2) + seg * 16);
            const size_t ga = (size_t)(bm + row) * DMODEL + kb + seg * 8;
            const size_t gb = (size_t)(bn + row) * DMODEL + kb + seg * 8;
            CP_ASYNC16(d,                 g_ahi + ga);
            CP_ASYNC16(d + MAT_BYTES,     g_alo + ga);
            CP_ASYNC16(d + 2 * MAT_BYTES, g_bhi + gb);
            CP_ASYNC16(d + 3 * MAT_BYTES, g_blo + gb);
        }
    };

    issue_chunk(0, 0);
    CP_COMMIT();
    issue_chunk(1, 1);
    CP_COMMIT();

    for (int kc = 0; kc < NCHUNK; kc++) {
        CP_WAIT1();
        __syncthreads();

        const uint32_t sAh = sbase + (uint32_t)(kc % 3) * GSTAGE_BYTES;
        const uint32_t sAl = sAh + MAT_BYTES;
        const uint32_t sBh = sAh + 2 * MAT_BYTES;
        const uint32_t sBl = sAh + 3 * MAT_BYTES;

        #pragma unroll
        for (int ks = 0; ks < 2; ks++) {
            const int k0 = ks * 16;
            uint32_t ah[2][4], al[2][4];
            #pragma unroll
            for (int mt = 0; mt < 2; mt++) {
                const uint32_t rel = (uint32_t)((wm + mt * 16) * ROWP + k0 + offA) * 2;
                ldsm4(ah[mt], sAh + rel);
                ldsm4(al[mt], sAl + rel);
            }
            #pragma unroll
            for (int ntp = 0; ntp < 4; ntp++) {
                const uint32_t rel = (uint32_t)((wn + ntp * 16) * ROWP + k0 + offB) * 2;
                uint32_t bh2[4], bl2[4];
                ldsm4(bh2, sBh + rel);
                ldsm4(bl2, sBl + rel);
                #pragma unroll
                for (int mt = 0; mt < 2; mt++) {
                    mma16816(acc[mt][2*ntp],   ah[mt], bh2);
                    mma16816(acc[mt][2*ntp],   ah[mt], bl2);
                    mma16816(acc[mt][2*ntp],   al[mt], bh2);
                    mma16816(acc[mt][2*ntp+1], ah[mt], bh2 + 2);
                    mma16816(acc[mt][2*ntp+1], ah[mt], bl2 + 2);
                    mma16816(acc[mt][2*ntp+1], al[mt], bh2 + 2);
                }
            }
        }

        if (kc + 2 < NCHUNK) issue_chunk(kc + 2, (kc + 2) % 3);
        CP_COMMIT();
    }

    #pragma unroll
    for (int mt = 0; mt < 2; mt++) {
        const int row0 = bm + wm + mt * 16 + g;
        #pragma unroll
        for (int nt = 0; nt < 8; nt++) {
            const int col0 = bn + wn + nt * 8 + t2;
            const float b0 = bias[col0], b1 = bias[col0 + 1];
            float2 o01 = { acc[mt][nt][0] + b0, acc[mt][nt][1] + b1 };
            float2 o23 = { acc[mt][nt][2] + b0, acc[mt][nt][3] + b1 };
            *(float2*)(C + (size_t)row0 * DMODEL + col0) = o01;
            *(float2*)(C + (size_t)(row0 + 8) * DMODEL + col0) = o23;
        }
    }
}

// ---------------------------------------------------------------------------
// Launch
// ---------------------------------------------------------------------------
extern "C" void kernel_launch(void* const* d_in, const int* in_sizes, int n_in,
                              void* d_out, int out_size)
{
    const float* residual = (const float*)d_in[0];
    const float* q        = (const float*)d_in[1];
    const float* k        = (const float*)d_in[2];
    const float* v        = (const float*)d_in[3];
    const float* W_O      = (const float*)d_in[4];
    const float* b_O      = (const float*)d_in[5];

    float* out = (float*)d_out;
    const int res_elems = BATCH * SEQ * DMODEL;

    const int n4 = res_elems / 4;
    copy_kernel<<<(n4 + 255) / 256, 256>>>(residual, out, n4);

    // Operand pre-conversion
    wsplit_kernel<<<dim3(32, 32), dim3(32, 8)>>>(W_O);
    const int kn = BATCH * SEQ * NHEADS * DHEAD / 2;
    ksplit_kernel<<<(kn + 255) / 256, 256>>>(k);
    vtsplit_kernel<<<dim3(SEQ / 32, DHEAD / 32, BATCH * NHEADS), dim3(32, 8)>>>(v);

    // Tensor-core attention -> g_ahi/g_alo
    cudaFuncSetAttribute(attn_tc_kernel,
                         cudaFuncAttributeMaxDynamicSharedMemorySize, ATT_SMEM);
    attn_tc_kernel<<<dim3(SEQ / 128, NHEADS, BATCH), 256, ATT_SMEM>>>(q);

    // Tensor-core projection
    cudaFuncSetAttribute(gemm_tc_kernel,
                         cudaFuncAttributeMaxDynamicSharedMemorySize, GEMM_SMEM);
    gemm_tc_kernel<<<dim3(DMODEL / 128, (BATCH * SEQ) / 128), 256, GEMM_SMEM>>>(
        b_O, out + res_elems);
}